// round 5
// baseline (speedup 1.0000x reference)
#include <cuda_runtime.h>
#include <math.h>

#define B_SZ 4
#define T_SZ 2048
#define DM   1024
#define NH   16
#define DH   64
#define HALF 32   // DH/2

// ---------------- scratch (device globals; no runtime allocation) ----------------
__device__ float g_q[B_SZ*NH*T_SZ*DH];     // [B,H,T,DH], RoPE applied
__device__ float g_k[B_SZ*NH*T_SZ*DH];     // [B,H,T,DH], RoPE applied
__device__ float g_v[B_SZ*NH*T_SZ*DH];     // [B,H,T,DH]
__device__ float g_attn[B_SZ*T_SZ*DM];     // [B,T,C] attention output
__device__ float g_cos[T_SZ*HALF];
__device__ float g_sin[T_SZ*HALF];

// ---------------- kernel 0: RoPE tables (double precision) ----------------
__global__ void rope_table_kernel() {
    int idx = blockIdx.x * blockDim.x + threadIdx.x;
    if (idx >= T_SZ * HALF) return;
    int t = idx / HALF;
    int j = idx % HALF;
    double inv = pow(10000.0, -(double)j / (double)HALF);
    double ang = (double)t * inv;
    g_cos[idx] = (float)cos(ang);
    g_sin[idx] = (float)sin(ang);
}

// ---------------- kernel 1: QKV GEMM (8192x1024 @ 1024x3072) + RoPE epilogue ----
// Block tile 128x128, K-tile 16, 256 threads, 8x8 per thread as 2x2 blocks of 4x4.
__global__ __launch_bounds__(256) void qkv_gemm_kernel(const float* __restrict__ x,
                                                       const float* __restrict__ W) {
    __shared__ float As[16][128];   // As[kk][row]
    __shared__ float Bs[16][128];   // Bs[kk][col]
    const int tid = threadIdx.x;
    const int tx = tid & 15, ty = tid >> 4;
    const int row0 = blockIdx.y * 128;
    const int col0 = blockIdx.x * 128;

    float acc[2][2][4][4];
#pragma unroll
    for (int a = 0; a < 2; a++)
#pragma unroll
        for (int b = 0; b < 2; b++)
#pragma unroll
            for (int i = 0; i < 4; i++)
#pragma unroll
                for (int j = 0; j < 4; j++) acc[a][b][i][j] = 0.f;

    const int alr = tid >> 1;           // 0..127 row of A tile
    const int alk = (tid & 1) * 8;      // kk chunk
    const int bk  = tid >> 4;           // 0..15 kk of B tile
    const int bc  = (tid & 15) * 4;     // col chunk

    for (int k0 = 0; k0 < DM; k0 += 16) {
        float4 a0 = *(const float4*)&x[(row0 + alr) * DM + k0 + alk];
        float4 a1 = *(const float4*)&x[(row0 + alr) * DM + k0 + alk + 4];
        As[alk+0][alr] = a0.x; As[alk+1][alr] = a0.y; As[alk+2][alr] = a0.z; As[alk+3][alr] = a0.w;
        As[alk+4][alr] = a1.x; As[alk+5][alr] = a1.y; As[alk+6][alr] = a1.z; As[alk+7][alr] = a1.w;
        *(float4*)&Bs[bk][bc]      = *(const float4*)&W[(k0 + bk) * 3072 + col0 + bc];
        *(float4*)&Bs[bk][bc + 64] = *(const float4*)&W[(k0 + bk) * 3072 + col0 + bc + 64];
        __syncthreads();
#pragma unroll
        for (int kk = 0; kk < 16; kk++) {
            float4 af0 = *(float4*)&As[kk][ty*4];
            float4 af1 = *(float4*)&As[kk][ty*4 + 64];
            float4 bf0 = *(float4*)&Bs[kk][tx*4];
            float4 bf1 = *(float4*)&Bs[kk][tx*4 + 64];
            float ar[2][4] = {{af0.x,af0.y,af0.z,af0.w},{af1.x,af1.y,af1.z,af1.w}};
            float br[2][4] = {{bf0.x,bf0.y,bf0.z,bf0.w},{bf1.x,bf1.y,bf1.z,bf1.w}};
#pragma unroll
            for (int a = 0; a < 2; a++)
#pragma unroll
                for (int i = 0; i < 4; i++)
#pragma unroll
                    for (int b = 0; b < 2; b++)
#pragma unroll
                        for (int j = 0; j < 4; j++)
                            acc[a][b][i][j] = fmaf(ar[a][i], br[b][j], acc[a][b][i][j]);
        }
        __syncthreads();
    }

    // epilogue: apply RoPE to q,k; scatter into [B,H,T,DH]
#pragma unroll
    for (int a = 0; a < 2; a++) {
#pragma unroll
        for (int b = 0; b < 2; b++) {
            const int cbase = col0 + b * 64 + tx * 4;
            const int which = cbase / DM;               // 0=q 1=k 2=v
            const int h = (cbase % DM) / DH;
            const int d0 = tx * 4;                      // (cbase % 64), 4-aligned
            const int j0 = d0 >> 1;
            float* dst = (which == 0) ? g_q : ((which == 1) ? g_k : g_v);
#pragma unroll
            for (int i = 0; i < 4; i++) {
                const int rg = row0 + a * 64 + ty * 4 + i;
                const int bb = rg >> 11;
                const int t  = rg & (T_SZ - 1);
                float v0 = acc[a][b][i][0], v1 = acc[a][b][i][1];
                float v2 = acc[a][b][i][2], v3 = acc[a][b][i][3];
                if (which < 2) {
                    const float c0 = g_cos[t*HALF + j0],     s0 = g_sin[t*HALF + j0];
                    const float c1 = g_cos[t*HALF + j0 + 1], s1 = g_sin[t*HALF + j0 + 1];
                    const float r0 = v0*c0 - v1*s0;
                    const float r1 = v0*s0 + v1*c0;
                    const float r2 = v2*c1 - v3*s1;
                    const float r3 = v2*s1 + v3*c1;
                    v0 = r0; v1 = r1; v2 = r2; v3 = r3;
                }
                const int idx = ((bb * NH + h) * T_SZ + t) * DH + d0;
                *(float4*)&dst[idx] = make_float4(v0, v1, v2, v3);
            }
        }
    }
}

// ---------------- kernel 2: flash attention, fp32, 64x64 tiles ----------------
// grid: (T/64 query tiles, B*H). 256 threads = 16x16, each owns 4 rows x 4 cols.
__global__ __launch_bounds__(256) void attn_kernel() {
    __shared__ float Qs[64][64];   // Qs[d][row]
    __shared__ float KP[64][64];   // K tile as [d][key], then reused as P [row][key]
    __shared__ float Vs[64][64];   // Vs[key][d]
    const int tid = threadIdx.x;
    const int tx = tid & 15, ty = tid >> 4;
    const int qt = blockIdx.x;
    const int bh = blockIdx.y;
    const float* qptr = g_q + (bh * T_SZ + qt * 64) * DH;
    const float* kptr = g_k + bh * T_SZ * DH;
    const float* vptr = g_v + bh * T_SZ * DH;

    {   // load Q tile transposed
        const int row = tid >> 2;
        const int cc  = tid & 3;
#pragma unroll
        for (int u = 0; u < 4; u++) {
            const int d0 = (cc + 4 * u) * 4;
            float4 qv = *(const float4*)&qptr[row * DH + d0];
            Qs[d0+0][row] = qv.x; Qs[d0+1][row] = qv.y;
            Qs[d0+2][row] = qv.z; Qs[d0+3][row] = qv.w;
        }
    }

    float m[4], l[4], acc[4][4];
#pragma unroll
    for (int i = 0; i < 4; i++) {
        m[i] = -1e30f; l[i] = 0.f;
#pragma unroll
        for (int j = 0; j < 4; j++) acc[i][j] = 0.f;
    }

    for (int kt = 0; kt <= qt; kt++) {
        __syncthreads();   // prior-iter P/V reads done (also covers Q store, iter 0)
        {   // load K transposed + V
            const int row = tid >> 2;
            const int cc  = tid & 3;
#pragma unroll
            for (int u = 0; u < 4; u++) {
                const int d0 = (cc + 4 * u) * 4;
                float4 kv = *(const float4*)&kptr[(kt * 64 + row) * DH + d0];
                KP[d0+0][row] = kv.x; KP[d0+1][row] = kv.y;
                KP[d0+2][row] = kv.z; KP[d0+3][row] = kv.w;
                *(float4*)&Vs[row][d0] = *(const float4*)&vptr[(kt * 64 + row) * DH + d0];
            }
        }
        __syncthreads();

        // S = Q K^T
        float s[4][4];
#pragma unroll
        for (int i = 0; i < 4; i++)
#pragma unroll
            for (int j = 0; j < 4; j++) s[i][j] = 0.f;
#pragma unroll 16
        for (int d = 0; d < 64; d++) {
            float4 a = *(float4*)&Qs[d][ty*4];
            float4 b = *(float4*)&KP[d][tx*4];
            float ar[4] = {a.x, a.y, a.z, a.w};
            float br[4] = {b.x, b.y, b.z, b.w};
#pragma unroll
            for (int i = 0; i < 4; i++)
#pragma unroll
                for (int j = 0; j < 4; j++)
                    s[i][j] = fmaf(ar[i], br[j], s[i][j]);
        }

        // scale + mask (reference predicate)
        const int qb = qt * 64 + ty * 4;
        const int kb = kt * 64 + tx * 4;
#pragma unroll
        for (int i = 0; i < 4; i++) {
            const int q = qb + i;
            const bool qg = ((q & 63) == 0);
#pragma unroll
            for (int j = 0; j < 4; j++) {
                const int k = kb + j;
                const bool ok = (k <= q) && ((q - k) <= 127 || ((k & 63) == 0) || qg);
                s[i][j] = ok ? s[i][j] * 0.125f : -1.0e9f;
            }
        }

        // row max across the 16 tx-threads of each row
        float rm[4];
#pragma unroll
        for (int i = 0; i < 4; i++)
            rm[i] = fmaxf(fmaxf(s[i][0], s[i][1]), fmaxf(s[i][2], s[i][3]));
#pragma unroll
        for (int off = 8; off > 0; off >>= 1)
#pragma unroll
            for (int i = 0; i < 4; i++)
                rm[i] = fmaxf(rm[i], __shfl_xor_sync(0xffffffffu, rm[i], off));

        float sc[4];
#pragma unroll
        for (int i = 0; i < 4; i++) {
            const float mn = fmaxf(m[i], rm[i]);
            sc[i] = __expf(m[i] - mn);
            m[i] = mn;
        }
        float rs[4];
#pragma unroll
        for (int i = 0; i < 4; i++) {
            float r = 0.f;
#pragma unroll
            for (int j = 0; j < 4; j++) {
                const float p = __expf(s[i][j] - m[i]);
                s[i][j] = p;
                r += p;
            }
            rs[i] = r;
        }
#pragma unroll
        for (int off = 8; off > 0; off >>= 1)
#pragma unroll
            for (int i = 0; i < 4; i++)
                rs[i] += __shfl_xor_sync(0xffffffffu, rs[i], off);
#pragma unroll
        for (int i = 0; i < 4; i++) {
            l[i] = l[i] * sc[i] + rs[i];
#pragma unroll
            for (int j = 0; j < 4; j++) acc[i][j] *= sc[i];
        }

        __syncthreads();   // all phase-A reads of KP done before overwriting with P
#pragma unroll
        for (int i = 0; i < 4; i++)
            *(float4*)&KP[ty*4 + i][tx*4] = make_float4(s[i][0], s[i][1], s[i][2], s[i][3]);
        __syncthreads();

        // acc += P V
#pragma unroll 8
        for (int kk = 0; kk < 64; kk += 4) {
            float4 a0 = *(float4*)&KP[ty*4 + 0][kk];
            float4 a1 = *(float4*)&KP[ty*4 + 1][kk];
            float4 a2 = *(float4*)&KP[ty*4 + 2][kk];
            float4 a3 = *(float4*)&KP[ty*4 + 3][kk];
            float ar[4][4] = {{a0.x,a0.y,a0.z,a0.w},{a1.x,a1.y,a1.z,a1.w},
                              {a2.x,a2.y,a2.z,a2.w},{a3.x,a3.y,a3.z,a3.w}};
#pragma unroll
            for (int u = 0; u < 4; u++) {
                float4 b = *(float4*)&Vs[kk + u][tx*4];
                float br[4] = {b.x, b.y, b.z, b.w};
#pragma unroll
                for (int i = 0; i < 4; i++)
#pragma unroll
                    for (int j = 0; j < 4; j++)
                        acc[i][j] = fmaf(ar[i][u], br[j], acc[i][j]);
            }
        }
    }

    // normalize + scatter to [B,T,C]
    const int bb = bh >> 4, hh = bh & 15;
#pragma unroll
    for (int i = 0; i < 4; i++) {
        const int q = qt * 64 + ty * 4 + i;
        const float inv = 1.0f / l[i];
        const int idx = (bb * T_SZ + q) * DM + hh * DH + tx * 4;
        *(float4*)&g_attn[idx] = make_float4(acc[i][0]*inv, acc[i][1]*inv,
                                             acc[i][2]*inv, acc[i][3]*inv);
    }
}

// ---------------- kernel 3: out projection (8192x1024 @ 1024x1024) + bias -------
__global__ __launch_bounds__(256) void out_gemm_kernel(const float* __restrict__ W,
                                                       const float* __restrict__ bias,
                                                       float* __restrict__ out) {
    __shared__ float As[16][128];
    __shared__ float Bs[16][128];
    const int tid = threadIdx.x;
    const int tx = tid & 15, ty = tid >> 4;
    const int row0 = blockIdx.y * 128;
    const int col0 = blockIdx.x * 128;

    float acc[2][2][4][4];
#pragma unroll
    for (int a = 0; a < 2; a++)
#pragma unroll
        for (int b = 0; b < 2; b++)
#pragma unroll
            for (int i = 0; i < 4; i++)
#pragma unroll
                for (int j = 0; j < 4; j++) acc[a][b][i][j] = 0.f;

    const int alr = tid >> 1;
    const int alk = (tid & 1) * 8;
    const int bk  = tid >> 4;
    const int bc  = (tid & 15) * 4;

    for (int k0 = 0; k0 < DM; k0 += 16) {
        float4 a0 = *(const float4*)&g_attn[(row0 + alr) * DM + k0 + alk];
        float4 a1 = *(const float4*)&g_attn[(row0 + alr) * DM + k0 + alk + 4];
        As[alk+0][alr] = a0.x; As[alk+1][alr] = a0.y; As[alk+2][alr] = a0.z; As[alk+3][alr] = a0.w;
        As[alk+4][alr] = a1.x; As[alk+5][alr] = a1.y; As[alk+6][alr] = a1.z; As[alk+7][alr] = a1.w;
        *(float4*)&Bs[bk][bc]      = *(const float4*)&W[(k0 + bk) * DM + col0 + bc];
        *(float4*)&Bs[bk][bc + 64] = *(const float4*)&W[(k0 + bk) * DM + col0 + bc + 64];
        __syncthreads();
#pragma unroll
        for (int kk = 0; kk < 16; kk++) {
            float4 af0 = *(float4*)&As[kk][ty*4];
            float4 af1 = *(float4*)&As[kk][ty*4 + 64];
            float4 bf0 = *(float4*)&Bs[kk][tx*4];
            float4 bf1 = *(float4*)&Bs[kk][tx*4 + 64];
            float ar[2][4] = {{af0.x,af0.y,af0.z,af0.w},{af1.x,af1.y,af1.z,af1.w}};
            float br[2][4] = {{bf0.x,bf0.y,bf0.z,bf0.w},{bf1.x,bf1.y,bf1.z,bf1.w}};
#pragma unroll
            for (int a = 0; a < 2; a++)
#pragma unroll
                for (int i = 0; i < 4; i++)
#pragma unroll
                    for (int b = 0; b < 2; b++)
#pragma unroll
                        for (int j = 0; j < 4; j++)
                            acc[a][b][i][j] = fmaf(ar[a][i], br[b][j], acc[a][b][i][j]);
        }
        __syncthreads();
    }

#pragma unroll
    for (int a = 0; a < 2; a++) {
#pragma unroll
        for (int b = 0; b < 2; b++) {
            const int cbase = col0 + b * 64 + tx * 4;
            const float4 bv = *(const float4*)&bias[cbase];
#pragma unroll
            for (int i = 0; i < 4; i++) {
                const int rg = row0 + a * 64 + ty * 4 + i;
                *(float4*)&out[rg * DM + cbase] =
                    make_float4(acc[a][b][i][0] + bv.x, acc[a][b][i][1] + bv.y,
                                acc[a][b][i][2] + bv.z, acc[a][b][i][3] + bv.w);
            }
        }
    }
}

// ---------------- launch ----------------
extern "C" void kernel_launch(void* const* d_in, const int* in_sizes, int n_in,
                              void* d_out, int out_size) {
    const float *x = nullptr, *Wqkv = nullptr, *Wout = nullptr, *bout = nullptr;
    for (int i = 0; i < n_in; i++) {
        switch (in_sizes[i]) {
            case B_SZ*T_SZ*DM: x    = (const float*)d_in[i]; break;   // 8388608
            case DM*3*DM:      Wqkv = (const float*)d_in[i]; break;   // 3145728
            case DM*DM:        Wout = (const float*)d_in[i]; break;   // 1048576
            case DM:           bout = (const float*)d_in[i]; break;   // 1024
        }
    }
    float* out = (float*)d_out;

    rope_table_kernel<<<(T_SZ*HALF + 255) / 256, 256>>>();
    qkv_gemm_kernel<<<dim3(3*DM/128, B_SZ*T_SZ/128), 256>>>(x, Wqkv);
    attn_kernel<<<dim3(T_SZ/64, B_SZ*NH), 256>>>();
    out_gemm_kernel<<<dim3(DM/128, B_SZ*T_SZ/128), 256>>>(Wout, bout, out);
}

// round 6
// speedup vs baseline: 1.5724x; 1.5724x over previous
#include <cuda_runtime.h>
#include <math.h>

#define B_SZ 4
#define T_SZ 2048
#define DM   1024
#define NH   16
#define DH   64
#define HALF 32   // DH/2

// ---------------- scratch (device globals; no runtime allocation) ----------------
__device__ float g_q[B_SZ*NH*T_SZ*DH];     // [B,H,T,DH], RoPE applied
__device__ float g_k[B_SZ*NH*T_SZ*DH];     // [B,H,T,DH], RoPE applied
__device__ float g_v[B_SZ*NH*T_SZ*DH];     // [B,H,T,DH]
__device__ float g_attn[B_SZ*T_SZ*DM];     // [B,T,C] attention output
__device__ float g_cos[T_SZ*HALF];
__device__ float g_sin[T_SZ*HALF];
// split-K partials for global-query rows: 64 bh x 4 chunks x 32 rows
__device__ float g_pm[64*4*32];
__device__ float g_pl[64*4*32];
__device__ float g_pacc[64*4*32*64];

// ---------------- kernel 0: RoPE tables (double precision) ----------------
__global__ void rope_table_kernel() {
    int idx = blockIdx.x * blockDim.x + threadIdx.x;
    if (idx >= T_SZ * HALF) return;
    int t = idx / HALF;
    int j = idx % HALF;
    double inv = pow(10000.0, -(double)j / (double)HALF);
    double ang = (double)t * inv;
    g_cos[idx] = (float)cos(ang);
    g_sin[idx] = (float)sin(ang);
}

// ---------------- kernel 1: QKV GEMM (8192x1024 @ 1024x3072) + RoPE epilogue ----
// Block tile 128x128, K-tile 16, 256 threads, double-buffered smem (1 sync/iter).
__global__ __launch_bounds__(256, 2) void qkv_gemm_kernel(const float* __restrict__ x,
                                                          const float* __restrict__ W) {
    __shared__ float As[2][16][128];   // As[buf][kk][row]
    __shared__ float Bs[2][16][128];   // Bs[buf][kk][col]
    const int tid = threadIdx.x;
    const int tx = tid & 15, ty = tid >> 4;
    const int row0 = blockIdx.y * 128;
    const int col0 = blockIdx.x * 128;

    float acc[2][2][4][4];
#pragma unroll
    for (int a = 0; a < 2; a++)
#pragma unroll
        for (int b = 0; b < 2; b++)
#pragma unroll
            for (int i = 0; i < 4; i++)
#pragma unroll
                for (int j = 0; j < 4; j++) acc[a][b][i][j] = 0.f;

    const int alr = tid >> 1;           // 0..127 row of A tile
    const int alk = (tid & 1) * 8;      // kk chunk
    const int bk  = tid >> 4;           // 0..15 kk of B tile
    const int bc  = (tid & 15) * 4;     // col chunk
    const float* aptr = &x[(row0 + alr) * DM + alk];
    const float* bptr = &W[bk * 3072 + col0 + bc];

    {   // preload tile 0 into buf 0
        float4 a0 = *(const float4*)(aptr);
        float4 a1 = *(const float4*)(aptr + 4);
        As[0][alk+0][alr]=a0.x; As[0][alk+1][alr]=a0.y; As[0][alk+2][alr]=a0.z; As[0][alk+3][alr]=a0.w;
        As[0][alk+4][alr]=a1.x; As[0][alk+5][alr]=a1.y; As[0][alk+6][alr]=a1.z; As[0][alk+7][alr]=a1.w;
        *(float4*)&Bs[0][bk][bc]      = *(const float4*)(bptr);
        *(float4*)&Bs[0][bk][bc + 64] = *(const float4*)(bptr + 64);
    }
    __syncthreads();

    int buf = 0;
    for (int k0 = 0; k0 < DM; k0 += 16) {
        float4 pa0, pa1, pb0, pb1;
        const bool nxt = (k0 + 16) < DM;
        if (nxt) {
            pa0 = *(const float4*)(aptr + k0 + 16);
            pa1 = *(const float4*)(aptr + k0 + 20);
            pb0 = *(const float4*)(bptr + (size_t)(k0 + 16) * 3072);
            pb1 = *(const float4*)(bptr + (size_t)(k0 + 16) * 3072 + 64);
        }
#pragma unroll
        for (int kk = 0; kk < 16; kk++) {
            float4 af0 = *(float4*)&As[buf][kk][ty*4];
            float4 af1 = *(float4*)&As[buf][kk][ty*4 + 64];
            float4 bf0 = *(float4*)&Bs[buf][kk][tx*4];
            float4 bf1 = *(float4*)&Bs[buf][kk][tx*4 + 64];
            float ar[2][4] = {{af0.x,af0.y,af0.z,af0.w},{af1.x,af1.y,af1.z,af1.w}};
            float br[2][4] = {{bf0.x,bf0.y,bf0.z,bf0.w},{bf1.x,bf1.y,bf1.z,bf1.w}};
#pragma unroll
            for (int a = 0; a < 2; a++)
#pragma unroll
                for (int i = 0; i < 4; i++)
#pragma unroll
                    for (int b = 0; b < 2; b++)
#pragma unroll
                        for (int j = 0; j < 4; j++)
                            acc[a][b][i][j] = fmaf(ar[a][i], br[b][j], acc[a][b][i][j]);
        }
        if (nxt) {
            const int nb = buf ^ 1;
            As[nb][alk+0][alr]=pa0.x; As[nb][alk+1][alr]=pa0.y; As[nb][alk+2][alr]=pa0.z; As[nb][alk+3][alr]=pa0.w;
            As[nb][alk+4][alr]=pa1.x; As[nb][alk+5][alr]=pa1.y; As[nb][alk+6][alr]=pa1.z; As[nb][alk+7][alr]=pa1.w;
            *(float4*)&Bs[nb][bk][bc]      = pb0;
            *(float4*)&Bs[nb][bk][bc + 64] = pb1;
        }
        __syncthreads();
        buf ^= 1;
    }

    // epilogue: apply RoPE to q,k; scatter into [B,H,T,DH]
#pragma unroll
    for (int a = 0; a < 2; a++) {
#pragma unroll
        for (int b = 0; b < 2; b++) {
            const int cbase = col0 + b * 64 + tx * 4;
            const int which = cbase / DM;               // 0=q 1=k 2=v
            const int h = (cbase % DM) / DH;
            const int d0 = tx * 4;                      // (cbase % 64), 4-aligned
            const int j0 = d0 >> 1;
            float* dst = (which == 0) ? g_q : ((which == 1) ? g_k : g_v);
#pragma unroll
            for (int i = 0; i < 4; i++) {
                const int rg = row0 + a * 64 + ty * 4 + i;
                const int bb = rg >> 11;
                const int t  = rg & (T_SZ - 1);
                float v0 = acc[a][b][i][0], v1 = acc[a][b][i][1];
                float v2 = acc[a][b][i][2], v3 = acc[a][b][i][3];
                if (which < 2) {
                    const float c0 = g_cos[t*HALF + j0],     s0 = g_sin[t*HALF + j0];
                    const float c1 = g_cos[t*HALF + j0 + 1], s1 = g_sin[t*HALF + j0 + 1];
                    const float r0 = v0*c0 - v1*s0;
                    const float r1 = v0*s0 + v1*c0;
                    const float r2 = v2*c1 - v3*s1;
                    const float r3 = v2*s1 + v3*c1;
                    v0 = r0; v1 = r1; v2 = r2; v3 = r3;
                }
                const int idx = ((bb * NH + h) * T_SZ + t) * DH + d0;
                *(float4*)&dst[idx] = make_float4(v0, v1, v2, v3);
            }
        }
    }
}

// ---------------- shared attention tile body (64 rows x 64 cols) ----------------
// Assumes Qs/KP/Vs loaded and synced by caller. Does S=QK^T, mask, online softmax
// update, P->KP (with sync fence), acc += P V. Leaves no trailing sync.
__device__ __forceinline__ void attn_tile_body(
    float (&Qs)[64][64], float (&KP)[64][64], float (&Vs)[64][64],
    int tx, int ty, int qt, int kt, int jmax, bool global_tile,
    float (&m)[4], float (&l)[4], float (&acc)[4][4])
{
    float s[4][4];
#pragma unroll
    for (int i = 0; i < 4; i++)
#pragma unroll
        for (int j = 0; j < 4; j++) s[i][j] = 0.f;
#pragma unroll 16
    for (int d = 0; d < 64; d++) {
        float4 a = *(float4*)&Qs[d][ty*4];
        float4 b = *(float4*)&KP[d][tx*4];
        float ar[4] = {a.x, a.y, a.z, a.w};
        float br[4] = {b.x, b.y, b.z, b.w};
#pragma unroll
        for (int i = 0; i < 4; i++)
#pragma unroll
            for (int j = 0; j < 4; j++)
                s[i][j] = fmaf(ar[i], br[j], s[i][j]);
    }

    if (global_tile) {
        // columns are gathered global keys j (k = 64*j, all allowed); valid j <= jmax
#pragma unroll
        for (int i = 0; i < 4; i++)
#pragma unroll
            for (int j = 0; j < 4; j++) {
                const bool ok = (tx*4 + j) <= jmax;
                s[i][j] = ok ? s[i][j] * 0.125f : -1.0e9f;
            }
    } else {
        const int qb = qt * 64 + ty * 4;
        const int kb = kt * 64 + tx * 4;
#pragma unroll
        for (int i = 0; i < 4; i++) {
            const int q = qb + i;
            const bool qg = ((q & 63) == 0);
#pragma unroll
            for (int j = 0; j < 4; j++) {
                const int k = kb + j;
                const bool ok = (k <= q) && ((q - k) <= 127 || ((k & 63) == 0) || qg);
                s[i][j] = ok ? s[i][j] * 0.125f : -1.0e9f;
            }
        }
    }

    float rm[4];
#pragma unroll
    for (int i = 0; i < 4; i++)
        rm[i] = fmaxf(fmaxf(s[i][0], s[i][1]), fmaxf(s[i][2], s[i][3]));
#pragma unroll
    for (int off = 8; off > 0; off >>= 1)
#pragma unroll
        for (int i = 0; i < 4; i++)
            rm[i] = fmaxf(rm[i], __shfl_xor_sync(0xffffffffu, rm[i], off));

    float sc[4];
#pragma unroll
    for (int i = 0; i < 4; i++) {
        const float mn = fmaxf(m[i], rm[i]);
        sc[i] = __expf(m[i] - mn);
        m[i] = mn;
    }
    float rs[4];
#pragma unroll
    for (int i = 0; i < 4; i++) {
        float r = 0.f;
#pragma unroll
        for (int j = 0; j < 4; j++) {
            const float p = __expf(s[i][j] - m[i]);
            s[i][j] = p;
            r += p;
        }
        rs[i] = r;
    }
#pragma unroll
    for (int off = 8; off > 0; off >>= 1)
#pragma unroll
        for (int i = 0; i < 4; i++)
            rs[i] += __shfl_xor_sync(0xffffffffu, rs[i], off);
#pragma unroll
    for (int i = 0; i < 4; i++) {
        l[i] = l[i] * sc[i] + rs[i];
#pragma unroll
        for (int j = 0; j < 4; j++) acc[i][j] *= sc[i];
    }

    __syncthreads();   // all reads of KP (K^T) done before overwriting with P
#pragma unroll
    for (int i = 0; i < 4; i++)
        *(float4*)&KP[ty*4 + i][tx*4] = make_float4(s[i][0], s[i][1], s[i][2], s[i][3]);
    __syncthreads();

#pragma unroll 8
    for (int kk = 0; kk < 64; kk += 4) {
        float4 a0 = *(float4*)&KP[ty*4 + 0][kk];
        float4 a1 = *(float4*)&KP[ty*4 + 1][kk];
        float4 a2 = *(float4*)&KP[ty*4 + 2][kk];
        float4 a3 = *(float4*)&KP[ty*4 + 3][kk];
        float ar[4][4] = {{a0.x,a0.y,a0.z,a0.w},{a1.x,a1.y,a1.z,a1.w},
                          {a2.x,a2.y,a2.z,a2.w},{a3.x,a3.y,a3.z,a3.w}};
#pragma unroll
        for (int u = 0; u < 4; u++) {
            float4 b = *(float4*)&Vs[kk + u][tx*4];
            float br[4] = {b.x, b.y, b.z, b.w};
#pragma unroll
            for (int i = 0; i < 4; i++)
#pragma unroll
                for (int j = 0; j < 4; j++)
                    acc[i][j] = fmaf(ar[i][u], br[j], acc[i][j]);
        }
    }
}

// ---------------- kernel 2: sparse flash attention ----------------
// Mask: allowed(q,k) = k<=q && (q-k<=127 || k%64==0 || q%64==0).
// Dense tiles only for kt in [qt-2, qt] (local window). Distant tiles contribute
// only their global-key column k=64*j (j<=qt-3), gathered into ONE extra tile.
// Global-query rows (q%64==0) are wrong here; fixed up by attn_gq_* kernels.
__global__ __launch_bounds__(256) void attn_kernel() {
    __shared__ float Qs[64][64];   // Qs[d][row]
    __shared__ float KP[64][64];   // K^T tile then P
    __shared__ float Vs[64][64];   // Vs[key][d]
    const int tid = threadIdx.x;
    const int tx = tid & 15, ty = tid >> 4;
    const int qt = blockIdx.x;
    const int bh = blockIdx.y;
    const float* qptr = g_q + (bh * T_SZ + qt * 64) * DH;
    const float* kptr = g_k + bh * T_SZ * DH;
    const float* vptr = g_v + bh * T_SZ * DH;

    {   // load Q tile transposed
        const int row = tid >> 2;
        const int cc  = tid & 3;
#pragma unroll
        for (int u = 0; u < 4; u++) {
            const int d0 = (cc + 4 * u) * 4;
            float4 qv = *(const float4*)&qptr[row * DH + d0];
            Qs[d0+0][row] = qv.x; Qs[d0+1][row] = qv.y;
            Qs[d0+2][row] = qv.z; Qs[d0+3][row] = qv.w;
        }
    }

    float m[4], l[4], acc[4][4];
#pragma unroll
    for (int i = 0; i < 4; i++) {
        m[i] = -1e30f; l[i] = 0.f;
#pragma unroll
        for (int j = 0; j < 4; j++) acc[i][j] = 0.f;
    }

    if (qt >= 3) {
        const int jmax = qt - 3;
        // gather global keys k=64*j (j<=jmax) into KP (transposed) / Vs
        const int row = tid >> 2;
        const int cc  = tid & 3;
        const bool valid = (row <= jmax);
#pragma unroll
        for (int u = 0; u < 4; u++) {
            const int d0 = (cc + 4 * u) * 4;
            if (valid) {
                float4 kv = *(const float4*)&kptr[(row << 6) * DH + d0];
                KP[d0+0][row] = kv.x; KP[d0+1][row] = kv.y;
                KP[d0+2][row] = kv.z; KP[d0+3][row] = kv.w;
                *(float4*)&Vs[row][d0] = *(const float4*)&vptr[(row << 6) * DH + d0];
            } else {
                KP[d0+0][row] = 0.f; KP[d0+1][row] = 0.f;
                KP[d0+2][row] = 0.f; KP[d0+3][row] = 0.f;
                *(float4*)&Vs[row][d0] = make_float4(0.f, 0.f, 0.f, 0.f);
            }
        }
        __syncthreads();
        attn_tile_body(Qs, KP, Vs, tx, ty, qt, 0, jmax, true, m, l, acc);
    }

    const int kt0 = (qt >= 2) ? (qt - 2) : 0;
    for (int kt = kt0; kt <= qt; kt++) {
        __syncthreads();   // prior P/V reads done (also covers Q store on first pass)
        {   // load K transposed + V
            const int row = tid >> 2;
            const int cc  = tid & 3;
#pragma unroll
            for (int u = 0; u < 4; u++) {
                const int d0 = (cc + 4 * u) * 4;
                float4 kv = *(const float4*)&kptr[(kt * 64 + row) * DH + d0];
                KP[d0+0][row] = kv.x; KP[d0+1][row] = kv.y;
                KP[d0+2][row] = kv.z; KP[d0+3][row] = kv.w;
                *(float4*)&Vs[row][d0] = *(const float4*)&vptr[(kt * 64 + row) * DH + d0];
            }
        }
        __syncthreads();
        attn_tile_body(Qs, KP, Vs, tx, ty, qt, kt, 0, false, m, l, acc);
    }

    // normalize + scatter to [B,T,C]
    const int bb = bh >> 4, hh = bh & 15;
#pragma unroll
    for (int i = 0; i < 4; i++) {
        const int q = qt * 64 + ty * 4 + i;
        const float inv = 1.0f / l[i];
        const int idx = (bb * T_SZ + q) * DM + hh * DH + tx * 4;
        *(float4*)&g_attn[idx] = make_float4(acc[i][0]*inv, acc[i][1]*inv,
                                             acc[i][2]*inv, acc[i][3]*inv);
    }
}

// ---------------- kernel 2b: global-query rows, split-K partials ----------------
// Queries q=64*r (r=0..31) per (b,h) attend to ALL k<=q. grid=(64 bh, 4 key-chunks).
// Chunk kc covers key tiles kt=kc*8..kc*8+7. Rows with zero valid keys in a chunk
// produce m=-1e9 poison which the combine's exp(m-M)=0 neutralizes exactly.
__global__ __launch_bounds__(256) void attn_gq_partial() {
    __shared__ float Qs[64][32];   // Qs[d][r], r = global query index
    __shared__ float KP[64][64];
    __shared__ float Vs[64][64];
    const int tid = threadIdx.x;
    const int tx = tid & 15, ty = tid >> 4;
    const int bh = blockIdx.x;
    const int kc = blockIdx.y;
    const float* qbase = g_q + bh * T_SZ * DH;
    const float* kbase = g_k + bh * T_SZ * DH;
    const float* vbase = g_v + bh * T_SZ * DH;

    {   // load 32 global queries transposed
        const int r  = tid >> 3;
        const int d0 = (tid & 7) * 8;
        float4 q0 = *(const float4*)&qbase[(r << 6) * DH + d0];
        float4 q1 = *(const float4*)&qbase[(r << 6) * DH + d0 + 4];
        Qs[d0+0][r] = q0.x; Qs[d0+1][r] = q0.y; Qs[d0+2][r] = q0.z; Qs[d0+3][r] = q0.w;
        Qs[d0+4][r] = q1.x; Qs[d0+5][r] = q1.y; Qs[d0+6][r] = q1.z; Qs[d0+7][r] = q1.w;
    }

    float m[2] = {-1e30f, -1e30f}, l[2] = {0.f, 0.f};
    float acc[2][4];
#pragma unroll
    for (int i = 0; i < 2; i++)
#pragma unroll
        for (int j = 0; j < 4; j++) acc[i][j] = 0.f;

    for (int it = 0; it < 8; it++) {
        const int kt = kc * 8 + it;
        __syncthreads();   // protect Qs store (first pass) and prior KP/Vs reads
        {
            const int row = tid >> 2;
            const int cc  = tid & 3;
#pragma unroll
            for (int u = 0; u < 4; u++) {
                const int d0 = (cc + 4 * u) * 4;
                float4 kv = *(const float4*)&kbase[(kt * 64 + row) * DH + d0];
                KP[d0+0][row] = kv.x; KP[d0+1][row] = kv.y;
                KP[d0+2][row] = kv.z; KP[d0+3][row] = kv.w;
                *(float4*)&Vs[row][d0] = *(const float4*)&vbase[(kt * 64 + row) * DH + d0];
            }
        }
        __syncthreads();

        float s[2][4];
#pragma unroll
        for (int i = 0; i < 2; i++)
#pragma unroll
            for (int j = 0; j < 4; j++) s[i][j] = 0.f;
#pragma unroll 16
        for (int d = 0; d < 64; d++) {
            const float a0 = Qs[d][ty*2];
            const float a1 = Qs[d][ty*2 + 1];
            float4 b = *(float4*)&KP[d][tx*4];
            float br[4] = {b.x, b.y, b.z, b.w};
#pragma unroll
            for (int j = 0; j < 4; j++) {
                s[0][j] = fmaf(a0, br[j], s[0][j]);
                s[1][j] = fmaf(a1, br[j], s[1][j]);
            }
        }
        // mask: key k <= q = 64*r
#pragma unroll
        for (int i = 0; i < 2; i++) {
            const int qv = (ty*2 + i) << 6;
#pragma unroll
            for (int j = 0; j < 4; j++) {
                const int k = kt * 64 + tx*4 + j;
                s[i][j] = (k <= qv) ? s[i][j] * 0.125f : -1.0e9f;
            }
        }

        float rm[2];
#pragma unroll
        for (int i = 0; i < 2; i++)
            rm[i] = fmaxf(fmaxf(s[i][0], s[i][1]), fmaxf(s[i][2], s[i][3]));
#pragma unroll
        for (int off = 8; off > 0; off >>= 1)
#pragma unroll
            for (int i = 0; i < 2; i++)
                rm[i] = fmaxf(rm[i], __shfl_xor_sync(0xffffffffu, rm[i], off));

        float sc[2], rs[2];
#pragma unroll
        for (int i = 0; i < 2; i++) {
            const float mn = fmaxf(m[i], rm[i]);
            sc[i] = __expf(m[i] - mn);
            m[i] = mn;
            float r = 0.f;
#pragma unroll
            for (int j = 0; j < 4; j++) {
                const float p = __expf(s[i][j] - m[i]);
                s[i][j] = p;
                r += p;
            }
            rs[i] = r;
        }
#pragma unroll
        for (int off = 8; off > 0; off >>= 1)
#pragma unroll
            for (int i = 0; i < 2; i++)
                rs[i] += __shfl_xor_sync(0xffffffffu, rs[i], off);
#pragma unroll
        for (int i = 0; i < 2; i++) {
            l[i] = l[i] * sc[i] + rs[i];
#pragma unroll
            for (int j = 0; j < 4; j++) acc[i][j] *= sc[i];
        }

        __syncthreads();
#pragma unroll
        for (int i = 0; i < 2; i++)
            *(float4*)&KP[ty*2 + i][tx*4] = make_float4(s[i][0], s[i][1], s[i][2], s[i][3]);
        __syncthreads();

#pragma unroll 8
        for (int kk = 0; kk < 64; kk += 4) {
            float4 a0 = *(float4*)&KP[ty*2 + 0][kk];
            float4 a1 = *(float4*)&KP[ty*2 + 1][kk];
            float ar[2][4] = {{a0.x,a0.y,a0.z,a0.w},{a1.x,a1.y,a1.z,a1.w}};
#pragma unroll
            for (int u = 0; u < 4; u++) {
                float4 b = *(float4*)&Vs[kk + u][tx*4];
                float br[4] = {b.x, b.y, b.z, b.w};
#pragma unroll
                for (int i = 0; i < 2; i++)
#pragma unroll
                    for (int j = 0; j < 4; j++)
                        acc[i][j] = fmaf(ar[i][u], br[j], acc[i][j]);
            }
        }
    }

    const int base = (bh * 4 + kc) * 32;
#pragma unroll
    for (int i = 0; i < 2; i++) {
        const int r = ty*2 + i;
        *(float4*)&g_pacc[(base + r) * 64 + tx*4] =
            make_float4(acc[i][0], acc[i][1], acc[i][2], acc[i][3]);
        if (tx == 0) { g_pm[base + r] = m[i]; g_pl[base + r] = l[i]; }
    }
}

// ---------------- kernel 2c: merge split-K partials, overwrite global-q rows ----
__global__ __launch_bounds__(256) void attn_gq_combine() {
    const int bh = blockIdx.x;
    const int b = bh >> 4, h = bh & 15;
    for (int idx = threadIdx.x; idx < 32 * 64; idx += 256) {
        const int r = idx >> 6, d = idx & 63;
        float M = -1e30f;
#pragma unroll
        for (int kc = 0; kc < 4; kc++)
            M = fmaxf(M, g_pm[(bh*4 + kc)*32 + r]);
        float l = 0.f, o = 0.f;
#pragma unroll
        for (int kc = 0; kc < 4; kc++) {
            const int p = (bh*4 + kc)*32 + r;
            const float w = __expf(g_pm[p] - M);
            l += w * g_pl[p];
            o += w * g_pacc[p * 64 + d];
        }
        g_attn[(b * T_SZ + (r << 6)) * DM + h * DH + d] = o / l;
    }
}

// ---------------- kernel 3: out projection (8192x1024 @ 1024x1024) + bias -------
__global__ __launch_bounds__(256, 2) void out_gemm_kernel(const float* __restrict__ W,
                                                          const float* __restrict__ bias,
                                                          float* __restrict__ out) {
    __shared__ float As[2][16][128];
    __shared__ float Bs[2][16][128];
    const int tid = threadIdx.x;
    const int tx = tid & 15, ty = tid >> 4;
    const int row0 = blockIdx.y * 128;
    const int col0 = blockIdx.x * 128;

    float acc[2][2][4][4];
#pragma unroll
    for (int a = 0; a < 2; a++)
#pragma unroll
        for (int b = 0; b < 2; b++)
#pragma unroll
            for (int i = 0; i < 4; i++)
#pragma unroll
                for (int j = 0; j < 4; j++) acc[a][b][i][j] = 0.f;

    const int alr = tid >> 1;
    const int alk = (tid & 1) * 8;
    const int bk  = tid >> 4;
    const int bc  = (tid & 15) * 4;
    const float* aptr = &g_attn[(row0 + alr) * DM + alk];
    const float* bptr = &W[bk * DM + col0 + bc];

    {
        float4 a0 = *(const float4*)(aptr);
        float4 a1 = *(const float4*)(aptr + 4);
        As[0][alk+0][alr]=a0.x; As[0][alk+1][alr]=a0.y; As[0][alk+2][alr]=a0.z; As[0][alk+3][alr]=a0.w;
        As[0][alk+4][alr]=a1.x; As[0][alk+5][alr]=a1.y; As[0][alk+6][alr]=a1.z; As[0][alk+7][alr]=a1.w;
        *(float4*)&Bs[0][bk][bc]      = *(const float4*)(bptr);
        *(float4*)&Bs[0][bk][bc + 64] = *(const float4*)(bptr + 64);
    }
    __syncthreads();

    int buf = 0;
    for (int k0 = 0; k0 < DM; k0 += 16) {
        float4 pa0, pa1, pb0, pb1;
        const bool nxt = (k0 + 16) < DM;
        if (nxt) {
            pa0 = *(const float4*)(aptr + k0 + 16);
            pa1 = *(const float4*)(aptr + k0 + 20);
            pb0 = *(const float4*)(bptr + (size_t)(k0 + 16) * DM);
            pb1 = *(const float4*)(bptr + (size_t)(k0 + 16) * DM + 64);
        }
#pragma unroll
        for (int kk = 0; kk < 16; kk++) {
            float4 af0 = *(float4*)&As[buf][kk][ty*4];
            float4 af1 = *(float4*)&As[buf][kk][ty*4 + 64];
            float4 bf0 = *(float4*)&Bs[buf][kk][tx*4];
            float4 bf1 = *(float4*)&Bs[buf][kk][tx*4 + 64];
            float ar[2][4] = {{af0.x,af0.y,af0.z,af0.w},{af1.x,af1.y,af1.z,af1.w}};
            float br[2][4] = {{bf0.x,bf0.y,bf0.z,bf0.w},{bf1.x,bf1.y,bf1.z,bf1.w}};
#pragma unroll
            for (int a = 0; a < 2; a++)
#pragma unroll
                for (int i = 0; i < 4; i++)
#pragma unroll
                    for (int b = 0; b < 2; b++)
#pragma unroll
                        for (int j = 0; j < 4; j++)
                            acc[a][b][i][j] = fmaf(ar[a][i], br[b][j], acc[a][b][i][j]);
        }
        if (nxt) {
            const int nb = buf ^ 1;
            As[nb][alk+0][alr]=pa0.x; As[nb][alk+1][alr]=pa0.y; As[nb][alk+2][alr]=pa0.z; As[nb][alk+3][alr]=pa0.w;
            As[nb][alk+4][alr]=pa1.x; As[nb][alk+5][alr]=pa1.y; As[nb][alk+6][alr]=pa1.z; As[nb][alk+7][alr]=pa1.w;
            *(float4*)&Bs[nb][bk][bc]      = pb0;
            *(float4*)&Bs[nb][bk][bc + 64] = pb1;
        }
        __syncthreads();
        buf ^= 1;
    }

#pragma unroll
    for (int a = 0; a < 2; a++) {
#pragma unroll
        for (int b = 0; b < 2; b++) {
            const int cbase = col0 + b * 64 + tx * 4;
            const float4 bv = *(const float4*)&bias[cbase];
#pragma unroll
            for (int i = 0; i < 4; i++) {
                const int rg = row0 + a * 64 + ty * 4 + i;
                *(float4*)&out[rg * DM + cbase] =
                    make_float4(acc[a][b][i][0] + bv.x, acc[a][b][i][1] + bv.y,
                                acc[a][b][i][2] + bv.z, acc[a][b][i][3] + bv.w);
            }
        }
    }
}

// ---------------- launch ----------------
extern "C" void kernel_launch(void* const* d_in, const int* in_sizes, int n_in,
                              void* d_out, int out_size) {
    const float *x = nullptr, *Wqkv = nullptr, *Wout = nullptr, *bout = nullptr;
    for (int i = 0; i < n_in; i++) {
        switch (in_sizes[i]) {
            case B_SZ*T_SZ*DM: x    = (const float*)d_in[i]; break;   // 8388608
            case DM*3*DM:      Wqkv = (const float*)d_in[i]; break;   // 3145728
            case DM*DM:        Wout = (const float*)d_in[i]; break;   // 1048576
            case DM:           bout = (const float*)d_in[i]; break;   // 1024
        }
    }
    float* out = (float*)d_out;

    rope_table_kernel<<<(T_SZ*HALF + 255) / 256, 256>>>();
    qkv_gemm_kernel<<<dim3(3*DM/128, B_SZ*T_SZ/128), 256>>>(x, Wqkv);
    attn_kernel<<<dim3(T_SZ/64, B_SZ*NH), 256>>>();
    attn_gq_partial<<<dim3(B_SZ*NH, 4), 256>>>();
    attn_gq_combine<<<B_SZ*NH, 256>>>();
    out_gemm_kernel<<<dim3(DM/128, B_SZ*T_SZ/128), 256>>>(Wout, bout, out);
}

// round 8
// speedup vs baseline: 2.1927x; 1.3945x over previous
#include <cuda_runtime.h>
#include <cuda_bf16.h>
#include <math.h>

#define B_SZ 4
#define T_SZ 2048
#define DM   1024
#define NH   16
#define DH   64
#define HALF 32   // DH/2

typedef unsigned int u32;

// ---------------- scratch (device globals; no runtime allocation) ----------------
__device__ float g_q[B_SZ*NH*T_SZ*DH];     // [B,H,T,DH], RoPE applied
__device__ float g_k[B_SZ*NH*T_SZ*DH];     // [B,H,T,DH], RoPE applied
__device__ float g_v[B_SZ*NH*T_SZ*DH];     // [B,H,T,DH]
__device__ float g_attn[B_SZ*T_SZ*DM];     // [B,T,C] attention output
__device__ float g_cos[T_SZ*HALF];
__device__ float g_sin[T_SZ*HALF];
// split-K partials for global-query rows: 64 bh x 4 chunks x 32 rows
__device__ float g_pm[64*4*32];
__device__ float g_pl[64*4*32];
__device__ float g_pacc[64*4*32*64];

// ---------------- tensor-core helpers ----------------
__device__ __forceinline__ void ldsm_x4(u32& r0, u32& r1, u32& r2, u32& r3, const void* p) {
    u32 a = (u32)__cvta_generic_to_shared(p);
    asm volatile("ldmatrix.sync.aligned.m8n8.x4.shared.b16 {%0,%1,%2,%3}, [%4];"
                 : "=r"(r0), "=r"(r1), "=r"(r2), "=r"(r3) : "r"(a));
}

__device__ __forceinline__ void ldsm_x4_t(u32& r0, u32& r1, u32& r2, u32& r3, const void* p) {
    u32 a = (u32)__cvta_generic_to_shared(p);
    asm volatile("ldmatrix.sync.aligned.m8n8.x4.trans.shared.b16 {%0,%1,%2,%3}, [%4];"
                 : "=r"(r0), "=r"(r1), "=r"(r2), "=r"(r3) : "r"(a));
}

__device__ __forceinline__ void mma_bf16(float* d, const u32* a, const u32* b) {
    asm volatile("mma.sync.aligned.m16n8k16.row.col.f32.bf16.bf16.f32 "
                 "{%0,%1,%2,%3}, {%4,%5,%6,%7}, {%8,%9}, {%0,%1,%2,%3};"
                 : "+f"(d[0]), "+f"(d[1]), "+f"(d[2]), "+f"(d[3])
                 : "r"(a[0]), "r"(a[1]), "r"(a[2]), "r"(a[3]), "r"(b[0]), "r"(b[1]));
}

// convert 8 contiguous floats to bf16 hi/lo pairs, one 16B store each
__device__ __forceinline__ void cvt8_store(const float* v, __nv_bfloat16* hi, __nv_bfloat16* lo) {
    u32 hw[4];
    u32 lw[4];
#pragma unroll
    for (int i = 0; i < 4; i++) {
        __nv_bfloat16 h0 = __float2bfloat16(v[2*i]);
        __nv_bfloat16 h1 = __float2bfloat16(v[2*i+1]);
        __nv_bfloat16 l0 = __float2bfloat16(v[2*i]   - __bfloat162float(h0));
        __nv_bfloat16 l1 = __float2bfloat16(v[2*i+1] - __bfloat162float(h1));
        __nv_bfloat162 hp = __halves2bfloat162(h0, h1);
        __nv_bfloat162 lp = __halves2bfloat162(l0, l1);
        hw[i] = *(u32*)&hp;
        lw[i] = *(u32*)&lp;
    }
    *(uint4*)hi = make_uint4(hw[0], hw[1], hw[2], hw[3]);
    *(uint4*)lo = make_uint4(lw[0], lw[1], lw[2], lw[3]);
}

// ---------------- shared 128x128 bf16-split GEMM mainloop ----------------
// abase: A block origin (row-major, lda=DM). bbase: B block origin (row-major, ldb=LDB).
// Computes the full 1024-deep K loop into acc[4][4][4] (warp tile 64x32, m16n8 frags).
template<int LDB>
__device__ __forceinline__ void tc_gemm_body(const float* __restrict__ abase,
                                             const float* __restrict__ bbase,
                                             float (&acc)[4][4][4]) {
    __shared__ __align__(16) __nv_bfloat16 Ah[2][128][24];
    __shared__ __align__(16) __nv_bfloat16 Al[2][128][24];
    __shared__ __align__(16) __nv_bfloat16 Bh[2][16][136];
    __shared__ __align__(16) __nv_bfloat16 Bl[2][16][136];
    const int tid  = threadIdx.x;
    const int lane = tid & 31;
    const int warp = tid >> 5;
    const int wm = warp >> 2;          // 0..1
    const int wn = warp & 3;           // 0..3

    const int ar = tid >> 1;           // A: row 0..127
    const int ak = (tid & 1) * 8;      // A: k chunk 0/8
    const int br = tid >> 4;           // B: k row 0..15
    const int bc = (tid & 15) * 8;     // B: col chunk
    const float* aptr = abase + (size_t)ar * DM + ak;
    const float* bptr = bbase + (size_t)br * LDB + bc;

#pragma unroll
    for (int mi = 0; mi < 4; mi++)
#pragma unroll
        for (int ni = 0; ni < 4; ni++)
#pragma unroll
            for (int r = 0; r < 4; r++)
                acc[mi][ni][r] = 0.f;

    {   // preload k-tile 0 into buf 0
        float va[8];
        float vb[8];
        *(float4*)&va[0] = *(const float4*)(aptr);
        *(float4*)&va[4] = *(const float4*)(aptr + 4);
        *(float4*)&vb[0] = *(const float4*)(bptr);
        *(float4*)&vb[4] = *(const float4*)(bptr + 4);
        cvt8_store(va, &Ah[0][ar][ak], &Al[0][ar][ak]);
        cvt8_store(vb, &Bh[0][br][bc], &Bl[0][br][bc]);
    }
    __syncthreads();

    const int arow = (lane & 7) + ((lane >> 3) & 1) * 8;   // ldmatrix row within 16
    const int akk  = ((lane >> 4) & 1) * 8;                // ldmatrix k-half

    int buf = 0;
    for (int kt = 0; kt < DM / 16; kt++) {
        float va[8];
        float vb[8];
        const bool nxt = (kt < DM / 16 - 1);
        if (nxt) {
            const float* an = aptr + (kt + 1) * 16;
            const float* bn = bptr + (size_t)(kt + 1) * 16 * LDB;
            *(float4*)&va[0] = *(const float4*)(an);
            *(float4*)&va[4] = *(const float4*)(an + 4);
            *(float4*)&vb[0] = *(const float4*)(bn);
            *(float4*)&vb[4] = *(const float4*)(bn + 4);
        }

        u32 AH[4][4];
        u32 AL[4][4];
        u32 BH[4][2];
        u32 BL[4][2];
#pragma unroll
        for (int mi = 0; mi < 4; mi++) {
            ldsm_x4(AH[mi][0], AH[mi][1], AH[mi][2], AH[mi][3],
                    &Ah[buf][wm*64 + mi*16 + arow][akk]);
            ldsm_x4(AL[mi][0], AL[mi][1], AL[mi][2], AL[mi][3],
                    &Al[buf][wm*64 + mi*16 + arow][akk]);
        }
#pragma unroll
        for (int nj = 0; nj < 2; nj++) {
            u32 t0, t1, t2, t3;
            ldsm_x4_t(t0, t1, t2, t3, &Bh[buf][arow][wn*32 + nj*16 + akk]);
            BH[nj*2][0] = t0;
            BH[nj*2][1] = t1;
            BH[nj*2+1][0] = t2;
            BH[nj*2+1][1] = t3;
            ldsm_x4_t(t0, t1, t2, t3, &Bl[buf][arow][wn*32 + nj*16 + akk]);
            BL[nj*2][0] = t0;
            BL[nj*2][1] = t1;
            BL[nj*2+1][0] = t2;
            BL[nj*2+1][1] = t3;
        }
#pragma unroll
        for (int mi = 0; mi < 4; mi++) {
#pragma unroll
            for (int ni = 0; ni < 4; ni++) {
                mma_bf16(acc[mi][ni], AH[mi], BH[ni]);
                mma_bf16(acc[mi][ni], AH[mi], BL[ni]);
                mma_bf16(acc[mi][ni], AL[mi], BH[ni]);
            }
        }

        if (nxt) {
            const int nb = buf ^ 1;
            cvt8_store(va, &Ah[nb][ar][ak], &Al[nb][ar][ak]);
            cvt8_store(vb, &Bh[nb][br][bc], &Bl[nb][br][bc]);
        }
        __syncthreads();
        buf ^= 1;
    }
}

// ---------------- kernel 0: RoPE tables (double precision) ----------------
__global__ void rope_table_kernel() {
    int idx = blockIdx.x * blockDim.x + threadIdx.x;
    if (idx >= T_SZ * HALF) return;
    int t = idx / HALF;
    int j = idx % HALF;
    double inv = pow(10000.0, -(double)j / (double)HALF);
    double ang = (double)t * inv;
    g_cos[idx] = (float)cos(ang);
    g_sin[idx] = (float)sin(ang);
}

// ---------------- kernel 1: QKV GEMM (tensor cores) + RoPE epilogue ----------------
__global__ __launch_bounds__(256) void qkv_tc_kernel(const float* __restrict__ x,
                                                     const float* __restrict__ W) {
    const int row0 = blockIdx.y * 128;
    const int col0 = blockIdx.x * 128;
    float acc[4][4][4];
    tc_gemm_body<3072>(x + (size_t)row0 * DM, W + col0, acc);

    const int lane = threadIdx.x & 31;
    const int warp = threadIdx.x >> 5;
    const int wm = warp >> 2;
    const int wn = warp & 3;
    const int r0c = lane >> 2;
    const int cp  = (lane & 3) * 2;
    const int which = col0 >> 10;                      // 0=q 1=k 2=v
    float* dst = (which == 0) ? g_q : ((which == 1) ? g_k : g_v);
    const bool dorope = (which < 2);

#pragma unroll
    for (int mi = 0; mi < 4; mi++) {
#pragma unroll
        for (int half = 0; half < 2; half++) {
            const int gm = row0 + wm*64 + mi*16 + r0c + half*8;
            const int bb = gm >> 11;
            const int t  = gm & (T_SZ - 1);
#pragma unroll
            for (int ni = 0; ni < 4; ni++) {
                const int gn  = col0 + wn*32 + ni*8 + cp;
                const int rem = gn & 1023;
                const int h = rem >> 6;
                const int d = rem & 63;
                float v0 = acc[mi][ni][half*2 + 0];
                float v1 = acc[mi][ni][half*2 + 1];
                if (dorope) {
                    const int j = d >> 1;
                    const float c = g_cos[t*HALF + j];
                    const float s = g_sin[t*HALF + j];
                    const float re = v0*c - v1*s;
                    const float ro = v0*s + v1*c;
                    v0 = re;
                    v1 = ro;
                }
                *(float2*)&dst[((size_t)(bb*NH + h) * T_SZ + t) * DH + d] = make_float2(v0, v1);
            }
        }
    }
}

// ---------------- kernel 3: out projection (tensor cores) + bias ----------------
__global__ __launch_bounds__(256) void out_tc_kernel(const float* __restrict__ W,
                                                     const float* __restrict__ bias,
                                                     float* __restrict__ out) {
    const int row0 = blockIdx.y * 128;
    const int col0 = blockIdx.x * 128;
    float acc[4][4][4];
    tc_gemm_body<1024>(g_attn + (size_t)row0 * DM, W + col0, acc);

    const int lane = threadIdx.x & 31;
    const int warp = threadIdx.x >> 5;
    const int wm = warp >> 2;
    const int wn = warp & 3;
    const int r0c = lane >> 2;
    const int cp  = (lane & 3) * 2;

#pragma unroll
    for (int mi = 0; mi < 4; mi++) {
#pragma unroll
        for (int half = 0; half < 2; half++) {
            const int gm = row0 + wm*64 + mi*16 + r0c + half*8;
#pragma unroll
            for (int ni = 0; ni < 4; ni++) {
                const int gn = col0 + wn*32 + ni*8 + cp;
                const float b0 = bias[gn];
                const float b1 = bias[gn + 1];
                *(float2*)&out[(size_t)gm * DM + gn] =
                    make_float2(acc[mi][ni][half*2 + 0] + b0,
                                acc[mi][ni][half*2 + 1] + b1);
            }
        }
    }
}

// ---------------- shared attention tile body (64 rows x 64 cols) ----------------
__device__ __forceinline__ void attn_tile_body(
    float (&Qs)[64][64], float (&KP)[64][64], float (&Vs)[64][64],
    int tx, int ty, int qt, int kt, int jmax, bool global_tile,
    float (&m)[4], float (&l)[4], float (&acc)[4][4])
{
    float s[4][4];
#pragma unroll
    for (int i = 0; i < 4; i++)
#pragma unroll
        for (int j = 0; j < 4; j++) s[i][j] = 0.f;
#pragma unroll 16
    for (int d = 0; d < 64; d++) {
        float4 a = *(float4*)&Qs[d][ty*4];
        float4 b = *(float4*)&KP[d][tx*4];
        float ar[4] = {a.x, a.y, a.z, a.w};
        float br[4] = {b.x, b.y, b.z, b.w};
#pragma unroll
        for (int i = 0; i < 4; i++)
#pragma unroll
            for (int j = 0; j < 4; j++)
                s[i][j] = fmaf(ar[i], br[j], s[i][j]);
    }

    if (global_tile) {
#pragma unroll
        for (int i = 0; i < 4; i++)
#pragma unroll
            for (int j = 0; j < 4; j++) {
                const bool ok = (tx*4 + j) <= jmax;
                s[i][j] = ok ? s[i][j] * 0.125f : -1.0e9f;
            }
    } else {
        const int qb = qt * 64 + ty * 4;
        const int kb = kt * 64 + tx * 4;
#pragma unroll
        for (int i = 0; i < 4; i++) {
            const int q = qb + i;
            const bool qg = ((q & 63) == 0);
#pragma unroll
            for (int j = 0; j < 4; j++) {
                const int k = kb + j;
                const bool ok = (k <= q) && ((q - k) <= 127 || ((k & 63) == 0) || qg);
                s[i][j] = ok ? s[i][j] * 0.125f : -1.0e9f;
            }
        }
    }

    float rm[4];
#pragma unroll
    for (int i = 0; i < 4; i++)
        rm[i] = fmaxf(fmaxf(s[i][0], s[i][1]), fmaxf(s[i][2], s[i][3]));
#pragma unroll
    for (int off = 8; off > 0; off >>= 1)
#pragma unroll
        for (int i = 0; i < 4; i++)
            rm[i] = fmaxf(rm[i], __shfl_xor_sync(0xffffffffu, rm[i], off));

    float sc[4];
#pragma unroll
    for (int i = 0; i < 4; i++) {
        const float mn = fmaxf(m[i], rm[i]);
        sc[i] = __expf(m[i] - mn);
        m[i] = mn;
    }
    float rs[4];
#pragma unroll
    for (int i = 0; i < 4; i++) {
        float r = 0.f;
#pragma unroll
        for (int j = 0; j < 4; j++) {
            const float p = __expf(s[i][j] - m[i]);
            s[i][j] = p;
            r += p;
        }
        rs[i] = r;
    }
#pragma unroll
    for (int off = 8; off > 0; off >>= 1)
#pragma unroll
        for (int i = 0; i < 4; i++)
            rs[i] += __shfl_xor_sync(0xffffffffu, rs[i], off);
#pragma unroll
    for (int i = 0; i < 4; i++) {
        l[i] = l[i] * sc[i] + rs[i];
#pragma unroll
        for (int j = 0; j < 4; j++) acc[i][j] *= sc[i];
    }

    __syncthreads();
#pragma unroll
    for (int i = 0; i < 4; i++)
        *(float4*)&KP[ty*4 + i][tx*4] = make_float4(s[i][0], s[i][1], s[i][2], s[i][3]);
    __syncthreads();

#pragma unroll 8
    for (int kk = 0; kk < 64; kk += 4) {
        float4 a0 = *(float4*)&KP[ty*4 + 0][kk];
        float4 a1 = *(float4*)&KP[ty*4 + 1][kk];
        float4 a2 = *(float4*)&KP[ty*4 + 2][kk];
        float4 a3 = *(float4*)&KP[ty*4 + 3][kk];
        float ar[4][4] = {{a0.x,a0.y,a0.z,a0.w},{a1.x,a1.y,a1.z,a1.w},
                          {a2.x,a2.y,a2.z,a2.w},{a3.x,a3.y,a3.z,a3.w}};
#pragma unroll
        for (int u = 0; u < 4; u++) {
            float4 b = *(float4*)&Vs[kk + u][tx*4];
            float br[4] = {b.x, b.y, b.z, b.w};
#pragma unroll
            for (int i = 0; i < 4; i++)
#pragma unroll
                for (int j = 0; j < 4; j++)
                    acc[i][j] = fmaf(ar[i][u], br[j], acc[i][j]);
        }
    }
}

// ---------------- kernel 2: sparse flash attention ----------------
__global__ __launch_bounds__(256) void attn_kernel() {
    __shared__ float Qs[64][64];
    __shared__ float KP[64][64];
    __shared__ float Vs[64][64];
    const int tid = threadIdx.x;
    const int tx = tid & 15, ty = tid >> 4;
    const int qt = blockIdx.x;
    const int bh = blockIdx.y;
    const float* qptr = g_q + (bh * T_SZ + qt * 64) * DH;
    const float* kptr = g_k + bh * T_SZ * DH;
    const float* vptr = g_v + bh * T_SZ * DH;

    {
        const int row = tid >> 2;
        const int cc  = tid & 3;
#pragma unroll
        for (int u = 0; u < 4; u++) {
            const int d0 = (cc + 4 * u) * 4;
            float4 qv = *(const float4*)&qptr[row * DH + d0];
            Qs[d0+0][row] = qv.x; Qs[d0+1][row] = qv.y;
            Qs[d0+2][row] = qv.z; Qs[d0+3][row] = qv.w;
        }
    }

    float m[4], l[4], acc[4][4];
#pragma unroll
    for (int i = 0; i < 4; i++) {
        m[i] = -1e30f; l[i] = 0.f;
#pragma unroll
        for (int j = 0; j < 4; j++) acc[i][j] = 0.f;
    }

    if (qt >= 3) {
        const int jmax = qt - 3;
        const int row = tid >> 2;
        const int cc  = tid & 3;
        const bool valid = (row <= jmax);
#pragma unroll
        for (int u = 0; u < 4; u++) {
            const int d0 = (cc + 4 * u) * 4;
            if (valid) {
                float4 kv = *(const float4*)&kptr[(row << 6) * DH + d0];
                KP[d0+0][row] = kv.x; KP[d0+1][row] = kv.y;
                KP[d0+2][row] = kv.z; KP[d0+3][row] = kv.w;
                *(float4*)&Vs[row][d0] = *(const float4*)&vptr[(row << 6) * DH + d0];
            } else {
                KP[d0+0][row] = 0.f; KP[d0+1][row] = 0.f;
                KP[d0+2][row] = 0.f; KP[d0+3][row] = 0.f;
                *(float4*)&Vs[row][d0] = make_float4(0.f, 0.f, 0.f, 0.f);
            }
        }
        __syncthreads();
        attn_tile_body(Qs, KP, Vs, tx, ty, qt, 0, jmax, true, m, l, acc);
    }

    const int kt0 = (qt >= 2) ? (qt - 2) : 0;
    for (int kt = kt0; kt <= qt; kt++) {
        __syncthreads();
        {
            const int row = tid >> 2;
            const int cc  = tid & 3;
#pragma unroll
            for (int u = 0; u < 4; u++) {
                const int d0 = (cc + 4 * u) * 4;
                float4 kv = *(const float4*)&kptr[(kt * 64 + row) * DH + d0];
                KP[d0+0][row] = kv.x; KP[d0+1][row] = kv.y;
                KP[d0+2][row] = kv.z; KP[d0+3][row] = kv.w;
                *(float4*)&Vs[row][d0] = *(const float4*)&vptr[(kt * 64 + row) * DH + d0];
            }
        }
        __syncthreads();
        attn_tile_body(Qs, KP, Vs, tx, ty, qt, kt, 0, false, m, l, acc);
    }

    const int bb = bh >> 4, hh = bh & 15;
#pragma unroll
    for (int i = 0; i < 4; i++) {
        const int q = qt * 64 + ty * 4 + i;
        const float inv = 1.0f / l[i];
        const int idx = (bb * T_SZ + q) * DM + hh * DH + tx * 4;
        *(float4*)&g_attn[idx] = make_float4(acc[i][0]*inv, acc[i][1]*inv,
                                             acc[i][2]*inv, acc[i][3]*inv);
    }
}

// ---------------- kernel 2b: global-query rows, split-K partials ----------------
__global__ __launch_bounds__(256) void attn_gq_partial() {
    __shared__ float Qs[64][32];
    __shared__ float KP[64][64];
    __shared__ float Vs[64][64];
    const int tid = threadIdx.x;
    const int tx = tid & 15, ty = tid >> 4;
    const int bh = blockIdx.x;
    const int kc = blockIdx.y;
    const float* qbase = g_q + bh * T_SZ * DH;
    const float* kbase = g_k + bh * T_SZ * DH;
    const float* vbase = g_v + bh * T_SZ * DH;

    {
        const int r  = tid >> 3;
        const int d0 = (tid & 7) * 8;
        float4 q0 = *(const float4*)&qbase[(r << 6) * DH + d0];
        float4 q1 = *(const float4*)&qbase[(r << 6) * DH + d0 + 4];
        Qs[d0+0][r] = q0.x; Qs[d0+1][r] = q0.y; Qs[d0+2][r] = q0.z; Qs[d0+3][r] = q0.w;
        Qs[d0+4][r] = q1.x; Qs[d0+5][r] = q1.y; Qs[d0+6][r] = q1.z; Qs[d0+7][r] = q1.w;
    }

    float m[2] = {-1e30f, -1e30f}, l[2] = {0.f, 0.f};
    float acc[2][4];
#pragma unroll
    for (int i = 0; i < 2; i++)
#pragma unroll
        for (int j = 0; j < 4; j++) acc[i][j] = 0.f;

    for (int it = 0; it < 8; it++) {
        const int kt = kc * 8 + it;
        __syncthreads();
        {
            const int row = tid >> 2;
            const int cc  = tid & 3;
#pragma unroll
            for (int u = 0; u < 4; u++) {
                const int d0 = (cc + 4 * u) * 4;
                float4 kv = *(const float4*)&kbase[(kt * 64 + row) * DH + d0];
                KP[d0+0][row] = kv.x; KP[d0+1][row] = kv.y;
                KP[d0+2][row] = kv.z; KP[d0+3][row] = kv.w;
                *(float4*)&Vs[row][d0] = *(const float4*)&vbase[(kt * 64 + row) * DH + d0];
            }
        }
        __syncthreads();

        float s[2][4];
#pragma unroll
        for (int i = 0; i < 2; i++)
#pragma unroll
            for (int j = 0; j < 4; j++) s[i][j] = 0.f;
#pragma unroll 16
        for (int d = 0; d < 64; d++) {
            const float a0 = Qs[d][ty*2];
            const float a1 = Qs[d][ty*2 + 1];
            float4 b = *(float4*)&KP[d][tx*4];
            float br[4] = {b.x, b.y, b.z, b.w};
#pragma unroll
            for (int j = 0; j < 4; j++) {
                s[0][j] = fmaf(a0, br[j], s[0][j]);
                s[1][j] = fmaf(a1, br[j], s[1][j]);
            }
        }
#pragma unroll
        for (int i = 0; i < 2; i++) {
            const int qv = (ty*2 + i) << 6;
#pragma unroll
            for (int j = 0; j < 4; j++) {
                const int k = kt * 64 + tx*4 + j;
                s[i][j] = (k <= qv) ? s[i][j] * 0.125f : -1.0e9f;
            }
        }

        float rm[2];
#pragma unroll
        for (int i = 0; i < 2; i++)
            rm[i] = fmaxf(fmaxf(s[i][0], s[i][1]), fmaxf(s[i][2], s[i][3]));
#pragma unroll
        for (int off = 8; off > 0; off >>= 1)
#pragma unroll
            for (int i = 0; i < 2; i++)
                rm[i] = fmaxf(rm[i], __shfl_xor_sync(0xffffffffu, rm[i], off));

        float sc[2], rs[2];
#pragma unroll
        for (int i = 0; i < 2; i++) {
            const float mn = fmaxf(m[i], rm[i]);
            sc[i] = __expf(m[i] - mn);
            m[i] = mn;
            float r = 0.f;
#pragma unroll
            for (int j = 0; j < 4; j++) {
                const float p = __expf(s[i][j] - m[i]);
                s[i][j] = p;
                r += p;
            }
            rs[i] = r;
        }
#pragma unroll
        for (int off = 8; off > 0; off >>= 1)
#pragma unroll
            for (int i = 0; i < 2; i++)
                rs[i] += __shfl_xor_sync(0xffffffffu, rs[i], off);
#pragma unroll
        for (int i = 0; i < 2; i++) {
            l[i] = l[i] * sc[i] + rs[i];
#pragma unroll
            for (int j = 0; j < 4; j++) acc[i][j] *= sc[i];
        }

        __syncthreads();
#pragma unroll
        for (int i = 0; i < 2; i++)
            *(float4*)&KP[ty*2 + i][tx*4] = make_float4(s[i][0], s[i][1], s[i][2], s[i][3]);
        __syncthreads();

#pragma unroll 8
        for (int kk = 0; kk < 64; kk += 4) {
            float4 a0 = *(float4*)&KP[ty*2 + 0][kk];
            float4 a1 = *(float4*)&KP[ty*2 + 1][kk];
            float ar[2][4] = {{a0.x,a0.y,a0.z,a0.w},{a1.x,a1.y,a1.z,a1.w}};
#pragma unroll
            for (int u = 0; u < 4; u++) {
                float4 b = *(float4*)&Vs[kk + u][tx*4];
                float br[4] = {b.x, b.y, b.z, b.w};
#pragma unroll
                for (int i = 0; i < 2; i++)
#pragma unroll
                    for (int j = 0; j < 4; j++)
                        acc[i][j] = fmaf(ar[i][u], br[j], acc[i][j]);
            }
        }
    }

    const int base = (bh * 4 + kc) * 32;
#pragma unroll
    for (int i = 0; i < 2; i++) {
        const int r = ty*2 + i;
        *(float4*)&g_pacc[(base + r) * 64 + tx*4] =
            make_float4(acc[i][0], acc[i][1], acc[i][2], acc[i][3]);
        if (tx == 0) { g_pm[base + r] = m[i]; g_pl[base + r] = l[i]; }
    }
}

// ---------------- kernel 2c: merge split-K partials ----------------
__global__ __launch_bounds__(256) void attn_gq_combine() {
    const int bh = blockIdx.x;
    const int b = bh >> 4, h = bh & 15;
    for (int idx = threadIdx.x; idx < 32 * 64; idx += 256) {
        const int r = idx >> 6, d = idx & 63;
        float M = -1e30f;
#pragma unroll
        for (int kc = 0; kc < 4; kc++)
            M = fmaxf(M, g_pm[(bh*4 + kc)*32 + r]);
        float l = 0.f, o = 0.f;
#pragma unroll
        for (int kc = 0; kc < 4; kc++) {
            const int p = (bh*4 + kc)*32 + r;
            const float w = __expf(g_pm[p] - M);
            l += w * g_pl[p];
            o += w * g_pacc[p * 64 + d];
        }
        g_attn[(b * T_SZ + (r << 6)) * DM + h * DH + d] = o / l;
    }
}

// ---------------- launch ----------------
extern "C" void kernel_launch(void* const* d_in, const int* in_sizes, int n_in,
                              void* d_out, int out_size) {
    const float *x = 0;
    const float *Wqkv = 0;
    const float *Wout = 0;
    const float *bout = 0;
    for (int i = 0; i < n_in; i++) {
        switch (in_sizes[i]) {
            case B_SZ*T_SZ*DM: x    = (const float*)d_in[i]; break;   // 8388608
            case DM*3*DM:      Wqkv = (const float*)d_in[i]; break;   // 3145728
            case DM*DM:        Wout = (const float*)d_in[i]; break;   // 1048576
            case DM:           bout = (const float*)d_in[i]; break;   // 1024
        }
    }
    float* out = (float*)d_out;

    rope_table_kernel<<<(T_SZ*HALF + 255) / 256, 256>>>();
    qkv_tc_kernel<<<dim3(3*DM/128, B_SZ*T_SZ/128), 256>>>(x, Wqkv);
    attn_kernel<<<dim3(T_SZ/64, B_SZ*NH), 256>>>();
    attn_gq_partial<<<dim3(B_SZ*NH, 4), 256>>>();
    attn_gq_combine<<<B_SZ*NH, 256>>>();
    out_tc_kernel<<<dim3(DM/128, B_SZ*T_SZ/128), 256>>>(Wout, bout, out);
}

// round 9
// speedup vs baseline: 2.7278x; 1.2440x over previous
#include <cuda_runtime.h>
#include <cuda_bf16.h>
#include <math.h>

#define B_SZ 4
#define T_SZ 2048
#define DM   1024
#define NH   16
#define DH   64
#define HALF 32   // DH/2

typedef unsigned int u32;

// ---------------- scratch (device globals; no runtime allocation) ----------------
__device__ float g_q[B_SZ*NH*T_SZ*DH];     // [B,H,T,DH], RoPE applied
__device__ float g_k[B_SZ*NH*T_SZ*DH];     // [B,H,T,DH], RoPE applied
__device__ float g_v[B_SZ*NH*T_SZ*DH];     // [B,H,T,DH]
__device__ float g_attn[B_SZ*T_SZ*DM];     // [B,T,C] attention output
__device__ float g_cos[T_SZ*HALF];
__device__ float g_sin[T_SZ*HALF];
// split-K partials for global-query rows
__device__ float g_pm[64*4*32];
__device__ float g_pl[64*4*32];
__device__ float g_pacc[64*4*32*64];
// pre-converted bf16 hi/lo operands
__device__ __nv_bfloat16 g_xh[B_SZ*T_SZ*DM];
__device__ __nv_bfloat16 g_xl[B_SZ*T_SZ*DM];
__device__ __nv_bfloat16 g_wqh[DM*3*DM];
__device__ __nv_bfloat16 g_wql[DM*3*DM];
__device__ __nv_bfloat16 g_woh[DM*DM];
__device__ __nv_bfloat16 g_wol[DM*DM];
__device__ __nv_bfloat16 g_ah[B_SZ*T_SZ*DM];
__device__ __nv_bfloat16 g_al[B_SZ*T_SZ*DM];

// ---------------- GEMM tiling constants ----------------
#define KS        32          // k-step (bf16 elems)
#define NSTG      3
#define AH_OFF    0           // A hi: 128 rows x 40 bf16 (80B padded) = 10240B
#define AL_OFF    10240
#define BH_OFF    20480       // B hi: 32 rows x 136 bf16 (272B padded) = 8704B
#define BL_OFF    29184
#define STG_BYTES 37888
#define GEMM_SMEM (NSTG * STG_BYTES)   // 113664

// ---------------- tensor-core / async helpers ----------------
__device__ __forceinline__ void ldsm4(u32& r0, u32& r1, u32& r2, u32& r3, u32 a) {
    asm volatile("ldmatrix.sync.aligned.m8n8.x4.shared.b16 {%0,%1,%2,%3}, [%4];"
                 : "=r"(r0), "=r"(r1), "=r"(r2), "=r"(r3) : "r"(a));
}
__device__ __forceinline__ void ldsm4t(u32& r0, u32& r1, u32& r2, u32& r3, u32 a) {
    asm volatile("ldmatrix.sync.aligned.m8n8.x4.trans.shared.b16 {%0,%1,%2,%3}, [%4];"
                 : "=r"(r0), "=r"(r1), "=r"(r2), "=r"(r3) : "r"(a));
}
__device__ __forceinline__ void mma_bf16(float* d, const u32* a, const u32* b) {
    asm volatile("mma.sync.aligned.m16n8k16.row.col.f32.bf16.bf16.f32 "
                 "{%0,%1,%2,%3}, {%4,%5,%6,%7}, {%8,%9}, {%0,%1,%2,%3};"
                 : "+f"(d[0]), "+f"(d[1]), "+f"(d[2]), "+f"(d[3])
                 : "r"(a[0]), "r"(a[1]), "r"(a[2]), "r"(a[3]), "r"(b[0]), "r"(b[1]));
}
__device__ __forceinline__ void cpa16(u32 dst, const void* src) {
    asm volatile("cp.async.cg.shared.global [%0], [%1], 16;" :: "r"(dst), "l"(src) : "memory");
}
__device__ __forceinline__ void cpa_commit() {
    asm volatile("cp.async.commit_group;" ::: "memory");
}
template<int N> __device__ __forceinline__ void cpa_wait() {
    asm volatile("cp.async.wait_group %0;" :: "n"(N) : "memory");
}

// ---------------- kernel: fp32 -> bf16 hi/lo split ----------------
__global__ void cvt_split_kernel(const float* __restrict__ src,
                                 __nv_bfloat16* __restrict__ hi,
                                 __nv_bfloat16* __restrict__ lo, int n4) {
    int i = blockIdx.x * blockDim.x + threadIdx.x;
    if (i >= n4) return;
    float4 v = ((const float4*)src)[i];
    float vv[4] = {v.x, v.y, v.z, v.w};
    u32 hw[2];
    u32 lw[2];
#pragma unroll
    for (int p = 0; p < 2; p++) {
        __nv_bfloat16 h0 = __float2bfloat16(vv[2*p]);
        __nv_bfloat16 h1 = __float2bfloat16(vv[2*p+1]);
        __nv_bfloat16 l0 = __float2bfloat16(vv[2*p]   - __bfloat162float(h0));
        __nv_bfloat16 l1 = __float2bfloat16(vv[2*p+1] - __bfloat162float(h1));
        __nv_bfloat162 hp = __halves2bfloat162(h0, h1);
        __nv_bfloat162 lp = __halves2bfloat162(l0, l1);
        hw[p] = *(u32*)&hp;
        lw[p] = *(u32*)&lp;
    }
    ((uint2*)hi)[i] = make_uint2(hw[0], hw[1]);
    ((uint2*)lo)[i] = make_uint2(lw[0], lw[1]);
}

// ---------------- kernel 0: RoPE tables (double precision) ----------------
__global__ void rope_table_kernel() {
    int idx = blockIdx.x * blockDim.x + threadIdx.x;
    if (idx >= T_SZ * HALF) return;
    int t = idx / HALF;
    int j = idx % HALF;
    double inv = pow(10000.0, -(double)j / (double)HALF);
    double ang = (double)t * inv;
    g_cos[idx] = (float)cos(ang);
    g_sin[idx] = (float)sin(ang);
}

// ---------------- shared 128x128 bf16-split GEMM, cp.async 3-stage pipeline -----
// A hi/lo: row-major [*, DM]; B hi/lo: row-major [DM, LDB]. Block tile 128x128.
template<int LDB>
__device__ __forceinline__ void tc_gemm_bf16(
    const __nv_bfloat16* __restrict__ Ahg, const __nv_bfloat16* __restrict__ Alg,
    const __nv_bfloat16* __restrict__ Bhg, const __nv_bfloat16* __restrict__ Blg,
    float (&acc)[4][4][4])
{
    extern __shared__ char sm[];
    const u32 smb = (u32)__cvta_generic_to_shared(sm);
    const int tid  = threadIdx.x;
    const int lane = tid & 31;
    const int warp = tid >> 5;
    const int wm = warp >> 2;          // 0..1
    const int wn = warp & 3;           // 0..3
    const int arow = (lane & 7) + ((lane >> 3) & 1) * 8;
    const int akk  = ((lane >> 4) & 1) * 8;

    const int ar  = tid >> 1;          // A row 0..127
    const int ac  = (tid & 1) * 16;    // A elem offset within k-step
    const int brr = tid >> 3;          // B k-row 0..31
    const int bc  = (tid & 7) * 16;    // B elem offset within 128 cols

#pragma unroll
    for (int mi = 0; mi < 4; mi++)
#pragma unroll
        for (int ni = 0; ni < 4; ni++)
#pragma unroll
            for (int r = 0; r < 4; r++)
                acc[mi][ni][r] = 0.f;

    const u32 a_soff = (u32)(ar * 80 + ac * 2);
    const u32 b_soff = (u32)(brr * 272 + bc * 2);

#define ISSUE_STAGE(kt, st) do {                                                   \
        const __nv_bfloat16* ah = Ahg + (size_t)ar * DM + (kt) * KS + ac;          \
        const __nv_bfloat16* al = Alg + (size_t)ar * DM + (kt) * KS + ac;          \
        const __nv_bfloat16* bh = Bhg + (size_t)((kt) * KS + brr) * LDB + bc;      \
        const __nv_bfloat16* bl = Blg + (size_t)((kt) * KS + brr) * LDB + bc;      \
        u32 sb = smb + (st) * STG_BYTES;                                           \
        cpa16(sb + AH_OFF + a_soff,      ah);                                      \
        cpa16(sb + AH_OFF + a_soff + 16, ah + 8);                                  \
        cpa16(sb + AL_OFF + a_soff,      al);                                      \
        cpa16(sb + AL_OFF + a_soff + 16, al + 8);                                  \
        cpa16(sb + BH_OFF + b_soff,      bh);                                      \
        cpa16(sb + BH_OFF + b_soff + 16, bh + 8);                                  \
        cpa16(sb + BL_OFF + b_soff,      bl);                                      \
        cpa16(sb + BL_OFF + b_soff + 16, bl + 8);                                  \
        cpa_commit();                                                              \
    } while (0)

    ISSUE_STAGE(0, 0);
    ISSUE_STAGE(1, 1);

    const int KT = DM / KS;            // 32
    int st = 0;
    for (int kt = 0; kt < KT; kt++) {
        if (kt == KT - 1) cpa_wait<0>(); else cpa_wait<1>();
        __syncthreads();
        if (kt + 2 < KT) {
            const int kn = kt + 2;
            ISSUE_STAGE(kn, kn % NSTG);
        }

        const u32 sb = smb + st * STG_BYTES;
#pragma unroll
        for (int kh = 0; kh < 2; kh++) {
            u32 AH[4][4];
            u32 AL[4][4];
            u32 BH[4][2];
            u32 BL[4][2];
#pragma unroll
            for (int mi = 0; mi < 4; mi++) {
                const u32 adr = sb + (u32)((wm*64 + mi*16 + arow) * 80 + (kh*16 + akk) * 2);
                ldsm4(AH[mi][0], AH[mi][1], AH[mi][2], AH[mi][3], adr + AH_OFF);
                ldsm4(AL[mi][0], AL[mi][1], AL[mi][2], AL[mi][3], adr + AL_OFF);
            }
#pragma unroll
            for (int nj = 0; nj < 2; nj++) {
                const u32 bdr = sb + (u32)((kh*16 + arow) * 272 + (wn*32 + nj*16 + akk) * 2);
                u32 t0, t1, t2, t3;
                ldsm4t(t0, t1, t2, t3, bdr + BH_OFF);
                BH[nj*2][0] = t0;
                BH[nj*2][1] = t1;
                BH[nj*2+1][0] = t2;
                BH[nj*2+1][1] = t3;
                ldsm4t(t0, t1, t2, t3, bdr + BL_OFF);
                BL[nj*2][0] = t0;
                BL[nj*2][1] = t1;
                BL[nj*2+1][0] = t2;
                BL[nj*2+1][1] = t3;
            }
#pragma unroll
            for (int mi = 0; mi < 4; mi++) {
#pragma unroll
                for (int ni = 0; ni < 4; ni++) {
                    mma_bf16(acc[mi][ni], AH[mi], BH[ni]);
                    mma_bf16(acc[mi][ni], AH[mi], BL[ni]);
                    mma_bf16(acc[mi][ni], AL[mi], BH[ni]);
                }
            }
        }
        st = (st + 1) % NSTG;
    }
#undef ISSUE_STAGE
}

// ---------------- kernel 1: QKV GEMM (tensor cores) + RoPE epilogue ----------------
__global__ __launch_bounds__(256) void qkv_tc_kernel() {
    const int row0 = blockIdx.y * 128;
    const int col0 = blockIdx.x * 128;
    float acc[4][4][4];
    tc_gemm_bf16<3072>(g_xh + (size_t)row0 * DM, g_xl + (size_t)row0 * DM,
                       g_wqh + col0, g_wql + col0, acc);

    const int lane = threadIdx.x & 31;
    const int warp = threadIdx.x >> 5;
    const int wm = warp >> 2;
    const int wn = warp & 3;
    const int r0c = lane >> 2;
    const int cp  = (lane & 3) * 2;
    const int which = col0 >> 10;                      // 0=q 1=k 2=v
    float* dst = (which == 0) ? g_q : ((which == 1) ? g_k : g_v);
    const bool dorope = (which < 2);

#pragma unroll
    for (int mi = 0; mi < 4; mi++) {
#pragma unroll
        for (int half = 0; half < 2; half++) {
            const int gm = row0 + wm*64 + mi*16 + r0c + half*8;
            const int bb = gm >> 11;
            const int t  = gm & (T_SZ - 1);
#pragma unroll
            for (int ni = 0; ni < 4; ni++) {
                const int gn  = col0 + wn*32 + ni*8 + cp;
                const int rem = gn & 1023;
                const int h = rem >> 6;
                const int d = rem & 63;
                float v0 = acc[mi][ni][half*2 + 0];
                float v1 = acc[mi][ni][half*2 + 1];
                if (dorope) {
                    const int j = d >> 1;
                    const float c = g_cos[t*HALF + j];
                    const float s = g_sin[t*HALF + j];
                    const float re = v0*c - v1*s;
                    const float ro = v0*s + v1*c;
                    v0 = re;
                    v1 = ro;
                }
                *(float2*)&dst[((size_t)(bb*NH + h) * T_SZ + t) * DH + d] = make_float2(v0, v1);
            }
        }
    }
}

// ---------------- kernel 3: out projection (tensor cores) + bias ----------------
__global__ __launch_bounds__(256) void out_tc_kernel(const float* __restrict__ bias,
                                                     float* __restrict__ out) {
    const int row0 = blockIdx.y * 128;
    const int col0 = blockIdx.x * 128;
    float acc[4][4][4];
    tc_gemm_bf16<1024>(g_ah + (size_t)row0 * DM, g_al + (size_t)row0 * DM,
                       g_woh + col0, g_wol + col0, acc);

    const int lane = threadIdx.x & 31;
    const int warp = threadIdx.x >> 5;
    const int wm = warp >> 2;
    const int wn = warp & 3;
    const int r0c = lane >> 2;
    const int cp  = (lane & 3) * 2;

#pragma unroll
    for (int mi = 0; mi < 4; mi++) {
#pragma unroll
        for (int half = 0; half < 2; half++) {
            const int gm = row0 + wm*64 + mi*16 + r0c + half*8;
#pragma unroll
            for (int ni = 0; ni < 4; ni++) {
                const int gn = col0 + wn*32 + ni*8 + cp;
                const float b0 = bias[gn];
                const float b1 = bias[gn + 1];
                *(float2*)&out[(size_t)gm * DM + gn] =
                    make_float2(acc[mi][ni][half*2 + 0] + b0,
                                acc[mi][ni][half*2 + 1] + b1);
            }
        }
    }
}

// ---------------- shared attention tile body (64 rows x 64 cols) ----------------
__device__ __forceinline__ void attn_tile_body(
    float (&Qs)[64][64], float (&KP)[64][64], float (&Vs)[64][64],
    int tx, int ty, int qt, int kt, int jmax, bool global_tile,
    float (&m)[4], float (&l)[4], float (&acc)[4][4])
{
    float s[4][4];
#pragma unroll
    for (int i = 0; i < 4; i++)
#pragma unroll
        for (int j = 0; j < 4; j++) s[i][j] = 0.f;
#pragma unroll 16
    for (int d = 0; d < 64; d++) {
        float4 a = *(float4*)&Qs[d][ty*4];
        float4 b = *(float4*)&KP[d][tx*4];
        float ar[4] = {a.x, a.y, a.z, a.w};
        float br[4] = {b.x, b.y, b.z, b.w};
#pragma unroll
        for (int i = 0; i < 4; i++)
#pragma unroll
            for (int j = 0; j < 4; j++)
                s[i][j] = fmaf(ar[i], br[j], s[i][j]);
    }

    if (global_tile) {
#pragma unroll
        for (int i = 0; i < 4; i++)
#pragma unroll
            for (int j = 0; j < 4; j++) {
                const bool ok = (tx*4 + j) <= jmax;
                s[i][j] = ok ? s[i][j] * 0.125f : -1.0e9f;
            }
    } else {
        const int qb = qt * 64 + ty * 4;
        const int kb = kt * 64 + tx * 4;
#pragma unroll
        for (int i = 0; i < 4; i++) {
            const int q = qb + i;
            const bool qg = ((q & 63) == 0);
#pragma unroll
            for (int j = 0; j < 4; j++) {
                const int k = kb + j;
                const bool ok = (k <= q) && ((q - k) <= 127 || ((k & 63) == 0) || qg);
                s[i][j] = ok ? s[i][j] * 0.125f : -1.0e9f;
            }
        }
    }

    float rm[4];
#pragma unroll
    for (int i = 0; i < 4; i++)
        rm[i] = fmaxf(fmaxf(s[i][0], s[i][1]), fmaxf(s[i][2], s[i][3]));
#pragma unroll
    for (int off = 8; off > 0; off >>= 1)
#pragma unroll
        for (int i = 0; i < 4; i++)
            rm[i] = fmaxf(rm[i], __shfl_xor_sync(0xffffffffu, rm[i], off));

    float sc[4];
#pragma unroll
    for (int i = 0; i < 4; i++) {
        const float mn = fmaxf(m[i], rm[i]);
        sc[i] = __expf(m[i] - mn);
        m[i] = mn;
    }
    float rs[4];
#pragma unroll
    for (int i = 0; i < 4; i++) {
        float r = 0.f;
#pragma unroll
        for (int j = 0; j < 4; j++) {
            const float p = __expf(s[i][j] - m[i]);
            s[i][j] = p;
            r += p;
        }
        rs[i] = r;
    }
#pragma unroll
    for (int off = 8; off > 0; off >>= 1)
#pragma unroll
        for (int i = 0; i < 4; i++)
            rs[i] += __shfl_xor_sync(0xffffffffu, rs[i], off);
#pragma unroll
    for (int i = 0; i < 4; i++) {
        l[i] = l[i] * sc[i] + rs[i];
#pragma unroll
        for (int j = 0; j < 4; j++) acc[i][j] *= sc[i];
    }

    __syncthreads();
#pragma unroll
    for (int i = 0; i < 4; i++)
        *(float4*)&KP[ty*4 + i][tx*4] = make_float4(s[i][0], s[i][1], s[i][2], s[i][3]);
    __syncthreads();

#pragma unroll 8
    for (int kk = 0; kk < 64; kk += 4) {
        float4 a0 = *(float4*)&KP[ty*4 + 0][kk];
        float4 a1 = *(float4*)&KP[ty*4 + 1][kk];
        float4 a2 = *(float4*)&KP[ty*4 + 2][kk];
        float4 a3 = *(float4*)&KP[ty*4 + 3][kk];
        float ar[4][4] = {{a0.x,a0.y,a0.z,a0.w},{a1.x,a1.y,a1.z,a1.w},
                          {a2.x,a2.y,a2.z,a2.w},{a3.x,a3.y,a3.z,a3.w}};
#pragma unroll
        for (int u = 0; u < 4; u++) {
            float4 b = *(float4*)&Vs[kk + u][tx*4];
            float br[4] = {b.x, b.y, b.z, b.w};
#pragma unroll
            for (int i = 0; i < 4; i++)
#pragma unroll
                for (int j = 0; j < 4; j++)
                    acc[i][j] = fmaf(ar[i][u], br[j], acc[i][j]);
        }
    }
}

// ---------------- kernel 2: sparse flash attention ----------------
__global__ __launch_bounds__(256) void attn_kernel() {
    __shared__ float Qs[64][64];
    __shared__ float KP[64][64];
    __shared__ float Vs[64][64];
    const int tid = threadIdx.x;
    const int tx = tid & 15, ty = tid >> 4;
    const int qt = blockIdx.x;
    const int bh = blockIdx.y;
    const float* qptr = g_q + (bh * T_SZ + qt * 64) * DH;
    const float* kptr = g_k + bh * T_SZ * DH;
    const float* vptr = g_v + bh * T_SZ * DH;

    {
        const int row = tid >> 2;
        const int cc  = tid & 3;
#pragma unroll
        for (int u = 0; u < 4; u++) {
            const int d0 = (cc + 4 * u) * 4;
            float4 qv = *(const float4*)&qptr[row * DH + d0];
            Qs[d0+0][row] = qv.x; Qs[d0+1][row] = qv.y;
            Qs[d0+2][row] = qv.z; Qs[d0+3][row] = qv.w;
        }
    }

    float m[4], l[4], acc[4][4];
#pragma unroll
    for (int i = 0; i < 4; i++) {
        m[i] = -1e30f; l[i] = 0.f;
#pragma unroll
        for (int j = 0; j < 4; j++) acc[i][j] = 0.f;
    }

    if (qt >= 3) {
        const int jmax = qt - 3;
        const int row = tid >> 2;
        const int cc  = tid & 3;
        const bool valid = (row <= jmax);
#pragma unroll
        for (int u = 0; u < 4; u++) {
            const int d0 = (cc + 4 * u) * 4;
            if (valid) {
                float4 kv = *(const float4*)&kptr[(row << 6) * DH + d0];
                KP[d0+0][row] = kv.x; KP[d0+1][row] = kv.y;
                KP[d0+2][row] = kv.z; KP[d0+3][row] = kv.w;
                *(float4*)&Vs[row][d0] = *(const float4*)&vptr[(row << 6) * DH + d0];
            } else {
                KP[d0+0][row] = 0.f; KP[d0+1][row] = 0.f;
                KP[d0+2][row] = 0.f; KP[d0+3][row] = 0.f;
                *(float4*)&Vs[row][d0] = make_float4(0.f, 0.f, 0.f, 0.f);
            }
        }
        __syncthreads();
        attn_tile_body(Qs, KP, Vs, tx, ty, qt, 0, jmax, true, m, l, acc);
    }

    const int kt0 = (qt >= 2) ? (qt - 2) : 0;
    for (int kt = kt0; kt <= qt; kt++) {
        __syncthreads();
        {
            const int row = tid >> 2;
            const int cc  = tid & 3;
#pragma unroll
            for (int u = 0; u < 4; u++) {
                const int d0 = (cc + 4 * u) * 4;
                float4 kv = *(const float4*)&kptr[(kt * 64 + row) * DH + d0];
                KP[d0+0][row] = kv.x; KP[d0+1][row] = kv.y;
                KP[d0+2][row] = kv.z; KP[d0+3][row] = kv.w;
                *(float4*)&Vs[row][d0] = *(const float4*)&vptr[(kt * 64 + row) * DH + d0];
            }
        }
        __syncthreads();
        attn_tile_body(Qs, KP, Vs, tx, ty, qt, kt, 0, false, m, l, acc);
    }

    const int bb = bh >> 4, hh = bh & 15;
#pragma unroll
    for (int i = 0; i < 4; i++) {
        const int q = qt * 64 + ty * 4 + i;
        const float inv = 1.0f / l[i];
        const int idx = (bb * T_SZ + q) * DM + hh * DH + tx * 4;
        *(float4*)&g_attn[idx] = make_float4(acc[i][0]*inv, acc[i][1]*inv,
                                             acc[i][2]*inv, acc[i][3]*inv);
    }
}

// ---------------- kernel 2b: global-query rows, split-K partials ----------------
__global__ __launch_bounds__(256) void attn_gq_partial() {
    __shared__ float Qs[64][32];
    __shared__ float KP[64][64];
    __shared__ float Vs[64][64];
    const int tid = threadIdx.x;
    const int tx = tid & 15, ty = tid >> 4;
    const int bh = blockIdx.x;
    const int kc = blockIdx.y;
    const float* qbase = g_q + bh * T_SZ * DH;
    const float* kbase = g_k + bh * T_SZ * DH;
    const float* vbase = g_v + bh * T_SZ * DH;

    {
        const int r  = tid >> 3;
        const int d0 = (tid & 7) * 8;
        float4 q0 = *(const float4*)&qbase[(r << 6) * DH + d0];
        float4 q1 = *(const float4*)&qbase[(r << 6) * DH + d0 + 4];
        Qs[d0+0][r] = q0.x; Qs[d0+1][r] = q0.y; Qs[d0+2][r] = q0.z; Qs[d0+3][r] = q0.w;
        Qs[d0+4][r] = q1.x; Qs[d0+5][r] = q1.y; Qs[d0+6][r] = q1.z; Qs[d0+7][r] = q1.w;
    }

    float m[2] = {-1e30f, -1e30f}, l[2] = {0.f, 0.f};
    float acc[2][4];
#pragma unroll
    for (int i = 0; i < 2; i++)
#pragma unroll
        for (int j = 0; j < 4; j++) acc[i][j] = 0.f;

    for (int it = 0; it < 8; it++) {
        const int kt = kc * 8 + it;
        __syncthreads();
        {
            const int row = tid >> 2;
            const int cc  = tid & 3;
#pragma unroll
            for (int u = 0; u < 4; u++) {
                const int d0 = (cc + 4 * u) * 4;
                float4 kv = *(const float4*)&kbase[(kt * 64 + row) * DH + d0];
                KP[d0+0][row] = kv.x; KP[d0+1][row] = kv.y;
                KP[d0+2][row] = kv.z; KP[d0+3][row] = kv.w;
                *(float4*)&Vs[row][d0] = *(const float4*)&vbase[(kt * 64 + row) * DH + d0];
            }
        }
        __syncthreads();

        float s[2][4];
#pragma unroll
        for (int i = 0; i < 2; i++)
#pragma unroll
            for (int j = 0; j < 4; j++) s[i][j] = 0.f;
#pragma unroll 16
        for (int d = 0; d < 64; d++) {
            const float a0 = Qs[d][ty*2];
            const float a1 = Qs[d][ty*2 + 1];
            float4 b = *(float4*)&KP[d][tx*4];
            float br[4] = {b.x, b.y, b.z, b.w};
#pragma unroll
            for (int j = 0; j < 4; j++) {
                s[0][j] = fmaf(a0, br[j], s[0][j]);
                s[1][j] = fmaf(a1, br[j], s[1][j]);
            }
        }
#pragma unroll
        for (int i = 0; i < 2; i++) {
            const int qv = (ty*2 + i) << 6;
#pragma unroll
            for (int j = 0; j < 4; j++) {
                const int k = kt * 64 + tx*4 + j;
                s[i][j] = (k <= qv) ? s[i][j] * 0.125f : -1.0e9f;
            }
        }

        float rm[2];
#pragma unroll
        for (int i = 0; i < 2; i++)
            rm[i] = fmaxf(fmaxf(s[i][0], s[i][1]), fmaxf(s[i][2], s[i][3]));
#pragma unroll
        for (int off = 8; off > 0; off >>= 1)
#pragma unroll
            for (int i = 0; i < 2; i++)
                rm[i] = fmaxf(rm[i], __shfl_xor_sync(0xffffffffu, rm[i], off));

        float sc[2], rs[2];
#pragma unroll
        for (int i = 0; i < 2; i++) {
            const float mn = fmaxf(m[i], rm[i]);
            sc[i] = __expf(m[i] - mn);
            m[i] = mn;
            float r = 0.f;
#pragma unroll
            for (int j = 0; j < 4; j++) {
                const float p = __expf(s[i][j] - m[i]);
                s[i][j] = p;
                r += p;
            }
            rs[i] = r;
        }
#pragma unroll
        for (int off = 8; off > 0; off >>= 1)
#pragma unroll
            for (int i = 0; i < 2; i++)
                rs[i] += __shfl_xor_sync(0xffffffffu, rs[i], off);
#pragma unroll
        for (int i = 0; i < 2; i++) {
            l[i] = l[i] * sc[i] + rs[i];
#pragma unroll
            for (int j = 0; j < 4; j++) acc[i][j] *= sc[i];
        }

        __syncthreads();
#pragma unroll
        for (int i = 0; i < 2; i++)
            *(float4*)&KP[ty*2 + i][tx*4] = make_float4(s[i][0], s[i][1], s[i][2], s[i][3]);
        __syncthreads();

#pragma unroll 8
        for (int kk = 0; kk < 64; kk += 4) {
            float4 a0 = *(float4*)&KP[ty*2 + 0][kk];
            float4 a1 = *(float4*)&KP[ty*2 + 1][kk];
            float ar[2][4] = {{a0.x,a0.y,a0.z,a0.w},{a1.x,a1.y,a1.z,a1.w}};
#pragma unroll
            for (int u = 0; u < 4; u++) {
                float4 b = *(float4*)&Vs[kk + u][tx*4];
                float br[4] = {b.x, b.y, b.z, b.w};
#pragma unroll
                for (int i = 0; i < 2; i++)
#pragma unroll
                    for (int j = 0; j < 4; j++)
                        acc[i][j] = fmaf(ar[i][u], br[j], acc[i][j]);
            }
        }
    }

    const int base = (bh * 4 + kc) * 32;
#pragma unroll
    for (int i = 0; i < 2; i++) {
        const int r = ty*2 + i;
        *(float4*)&g_pacc[(base + r) * 64 + tx*4] =
            make_float4(acc[i][0], acc[i][1], acc[i][2], acc[i][3]);
        if (tx == 0) { g_pm[base + r] = m[i]; g_pl[base + r] = l[i]; }
    }
}

// ---------------- kernel 2c: merge split-K partials ----------------
__global__ __launch_bounds__(256) void attn_gq_combine() {
    const int bh = blockIdx.x;
    const int b = bh >> 4, h = bh & 15;
    for (int idx = threadIdx.x; idx < 32 * 64; idx += 256) {
        const int r = idx >> 6, d = idx & 63;
        float M = -1e30f;
#pragma unroll
        for (int kc = 0; kc < 4; kc++)
            M = fmaxf(M, g_pm[(bh*4 + kc)*32 + r]);
        float l = 0.f, o = 0.f;
#pragma unroll
        for (int kc = 0; kc < 4; kc++) {
            const int p = (bh*4 + kc)*32 + r;
            const float w = __expf(g_pm[p] - M);
            l += w * g_pl[p];
            o += w * g_pacc[p * 64 + d];
        }
        g_attn[(b * T_SZ + (r << 6)) * DM + h * DH + d] = o / l;
    }
}

// ---------------- launch ----------------
extern "C" void kernel_launch(void* const* d_in, const int* in_sizes, int n_in,
                              void* d_out, int out_size) {
    const float *x = 0;
    const float *Wqkv = 0;
    const float *Wout = 0;
    const float *bout = 0;
    for (int i = 0; i < n_in; i++) {
        switch (in_sizes[i]) {
            case B_SZ*T_SZ*DM: x    = (const float*)d_in[i]; break;   // 8388608
            case DM*3*DM:      Wqkv = (const float*)d_in[i]; break;   // 3145728
            case DM*DM:        Wout = (const float*)d_in[i]; break;   // 1048576
            case DM:           bout = (const float*)d_in[i]; break;   // 1024
        }
    }
    float* out = (float*)d_out;

    cudaFuncSetAttribute(qkv_tc_kernel, cudaFuncAttributeMaxDynamicSharedMemorySize, GEMM_SMEM);
    cudaFuncSetAttribute(out_tc_kernel, cudaFuncAttributeMaxDynamicSharedMemorySize, GEMM_SMEM);

    // device-global symbol addresses for cvt launches
    __nv_bfloat16 *xh, *xl, *wqh, *wql, *woh, *wol, *ah, *al;
    float* attn_f;
    cudaGetSymbolAddress((void**)&xh,  g_xh);
    cudaGetSymbolAddress((void**)&xl,  g_xl);
    cudaGetSymbolAddress((void**)&wqh, g_wqh);
    cudaGetSymbolAddress((void**)&wql, g_wql);
    cudaGetSymbolAddress((void**)&woh, g_woh);
    cudaGetSymbolAddress((void**)&wol, g_wol);
    cudaGetSymbolAddress((void**)&ah,  g_ah);
    cudaGetSymbolAddress((void**)&al,  g_al);
    cudaGetSymbolAddress((void**)&attn_f, g_attn);

    rope_table_kernel<<<(T_SZ*HALF + 255) / 256, 256>>>();
    cvt_split_kernel<<<(B_SZ*T_SZ*DM/4 + 255) / 256, 256>>>(x, xh, xl, B_SZ*T_SZ*DM/4);
    cvt_split_kernel<<<(DM*3*DM/4 + 255) / 256, 256>>>(Wqkv, wqh, wql, DM*3*DM/4);
    cvt_split_kernel<<<(DM*DM/4 + 255) / 256, 256>>>(Wout, woh, wol, DM*DM/4);

    qkv_tc_kernel<<<dim3(3*DM/128, B_SZ*T_SZ/128), 256, GEMM_SMEM>>>();
    attn_kernel<<<dim3(T_SZ/64, B_SZ*NH), 256>>>();
    attn_gq_partial<<<dim3(B_SZ*NH, 4), 256>>>();
    attn_gq_combine<<<B_SZ*NH, 256>>>();
    cvt_split_kernel<<<(B_SZ*T_SZ*DM/4 + 255) / 256, 256>>>(attn_f, ah, al, B_SZ*T_SZ*DM/4);
    out_tc_kernel<<<dim3(DM/128, B_SZ*T_SZ/128), 256, GEMM_SMEM>>>(bout, out);
}